// round 4
// baseline (speedup 1.0000x reference)
#include <cuda_runtime.h>
#include <cstdint>

#define B_   64
#define T_   4096
#define NIN  64
#define U_   128
#define NOUT 64
#define CCH  64
#define LCH  64

// ---------------------------------------------------------------------------
// Static device scratch
// ---------------------------------------------------------------------------
__device__ float g_Ky[B_ * T_ * U_];      // 128 MB
__device__ float g_ATt[U_ * U_];          // A transposed: ATt[u][k] = AT[k][u]
__device__ float g_E[B_ * CCH * U_];
__device__ float g_carry[B_ * CCH * U_];
__device__ float g_A2[U_ * U_], g_A4[U_ * U_], g_A8[U_ * U_];
__device__ float g_A16[U_ * U_], g_A32[U_ * U_], g_A64[U_ * U_];
__device__ float g_Wt[U_ * LCH * NOUT];   // [k][step][o]; W[s] = A^(s+1)@CyT

// ---------------------------------------------------------------------------
// Packed f32x2 helpers
// ---------------------------------------------------------------------------
__device__ __forceinline__ unsigned long long ffma2(unsigned long long a,
                                                    unsigned long long b,
                                                    unsigned long long c) {
    unsigned long long d;
    asm("fma.rn.f32x2 %0, %1, %2, %3;" : "=l"(d) : "l"(a), "l"(b), "l"(c));
    return d;
}
__device__ __forceinline__ unsigned long long dup2(float v) {
    unsigned long long r;
    asm("mov.b64 %0, {%1, %1};" : "=l"(r) : "f"(v));
    return r;
}
__device__ __forceinline__ unsigned long long pack2(float x, float y) {
    unsigned long long r;
    asm("mov.b64 %0, {%1, %2};" : "=l"(r) : "f"(x), "f"(y));
    return r;
}
__device__ __forceinline__ float2 unpack2(unsigned long long v) {
    float2 f;
    asm("mov.b64 {%0, %1}, %2;" : "=f"(f.x), "=f"(f.y) : "l"(v));
    return f;
}

// ---------------------------------------------------------------------------
// K1: Ky = x @ KT   (proven R1 kernel)
// ---------------------------------------------------------------------------
__global__ __launch_bounds__(128) void ky_kernel(const float* __restrict__ x,
                                                 const float* __restrict__ KT) {
    const int u = threadIdx.x;
    float kt[NIN];
#pragma unroll
    for (int n = 0; n < NIN; n++) kt[n] = KT[n * U_ + u];

    __shared__ __align__(16) float xs[NIN * 8];
    const int row0 = blockIdx.x * 256;

#pragma unroll 1
    for (int tile = 0; tile < 32; tile++) {
        const int r0 = row0 + tile * 8;
        float4 xv = reinterpret_cast<const float4*>(x + (size_t)r0 * NIN)[u];
        __syncthreads();
        {
            const int rr = u >> 4;
            const int n0 = (u & 15) * 4;
            xs[(n0 + 0) * 8 + rr] = xv.x;
            xs[(n0 + 1) * 8 + rr] = xv.y;
            xs[(n0 + 2) * 8 + rr] = xv.z;
            xs[(n0 + 3) * 8 + rr] = xv.w;
        }
        __syncthreads();

        unsigned long long acc[4] = {0ull, 0ull, 0ull, 0ull};
#pragma unroll
        for (int n = 0; n < NIN; n++) {
            unsigned long long kv = dup2(kt[n]);
            ulonglong2 a = *reinterpret_cast<const ulonglong2*>(&xs[n * 8]);
            ulonglong2 b = *reinterpret_cast<const ulonglong2*>(&xs[n * 8 + 4]);
            acc[0] = ffma2(a.x, kv, acc[0]);
            acc[1] = ffma2(a.y, kv, acc[1]);
            acc[2] = ffma2(b.x, kv, acc[2]);
            acc[3] = ffma2(b.y, kv, acc[3]);
        }
#pragma unroll
        for (int i = 0; i < 4; i++) {
            float2 f = unpack2(acc[i]);
            g_Ky[(size_t)(r0 + 2 * i)     * U_ + u] = f.x;
            g_Ky[(size_t)(r0 + 2 * i + 1) * U_ + u] = f.y;
        }
    }
}

// ---------------------------------------------------------------------------
// K2: transpose A -> g_ATt
// ---------------------------------------------------------------------------
__global__ __launch_bounds__(128) void transA_kernel(const float* __restrict__ AT) {
    // blockIdx.x = k, threadIdx.x = u ; read coalesced
    g_ATt[(size_t)threadIdx.x * U_ + blockIdx.x] =
        AT[(size_t)blockIdx.x * U_ + threadIdx.x];
}

// ---------------------------------------------------------------------------
// K3: scan.  s_{t+1}[u] = ky_t[u] + sum_k s_t[k] * AT[k][u]
// 8 batches/CTA, fused y_t = s_{t+1} @ CyT, emits chunk-end E.
// A streamed per-thread from L1-resident g_ATt row. ~55 regs, occ 4.
// ---------------------------------------------------------------------------
__global__ __launch_bounds__(128) void scan_kernel(const float* __restrict__ CyT,
                                                   float* __restrict__ y,
                                                   int bgbase) {
    const int c = blockIdx.x, bg = blockIdx.y + bgbase, u = threadIdx.x;
    const int b0 = bg * 8;

    __shared__ __align__(16) float s_sh[2][U_ * 8];   // 8 KB
    __shared__ __align__(16) float cy_sh[U_ * NOUT];  // 32 KB

    {   // stage CyT
        const float4* src = (const float4*)CyT;
        float4* dst = (float4*)cy_sh;
#pragma unroll
        for (int i = 0; i < 16; i++) dst[i * 128 + u] = src[i * 128 + u];
    }
#pragma unroll
    for (int j = 0; j < 8; j++) s_sh[0][u * 8 + j] = 0.f;
    __syncthreads();

    const float* __restrict__ arow = g_ATt + (size_t)u * U_;
    const int o = u & 63, bs = u >> 6;

    float kyc[8];
#pragma unroll
    for (int j = 0; j < 8; j++)
        kyc[j] = g_Ky[((size_t)(b0 + j) * T_ + c * LCH) * U_ + u];

    int p = 0;
#pragma unroll 1
    for (int step = 0; step < LCH; step++) {
        const int t = c * LCH + step;

        float kyn[8];
        if (step < LCH - 1) {
#pragma unroll
            for (int j = 0; j < 8; j++)
                kyn[j] = g_Ky[((size_t)(b0 + j) * T_ + t + 1) * U_ + u];
        } else {
#pragma unroll
            for (int j = 0; j < 8; j++) kyn[j] = 0.f;
        }

        unsigned long long acc[4];
#pragma unroll
        for (int i = 0; i < 4; i++) acc[i] = pack2(kyc[2 * i], kyc[2 * i + 1]);

#pragma unroll
        for (int k4 = 0; k4 < U_; k4 += 4) {
            const float4 a4 = *(const float4*)(arow + k4);
#pragma unroll
            for (int kk = 0; kk < 4; kk++) {
                const float av_f = (kk == 0) ? a4.x : (kk == 1) ? a4.y
                                 : (kk == 2) ? a4.z : a4.w;
                const unsigned long long av = dup2(av_f);
                const int k = k4 + kk;
                const ulonglong2 s01 = *(const ulonglong2*)&s_sh[p][k * 8];
                const ulonglong2 s23 = *(const ulonglong2*)&s_sh[p][k * 8 + 4];
                acc[0] = ffma2(s01.x, av, acc[0]);
                acc[1] = ffma2(s01.y, av, acc[1]);
                acc[2] = ffma2(s23.x, av, acc[2]);
                acc[3] = ffma2(s23.y, av, acc[3]);
            }
        }

        const int q = p ^ 1;
        {
            float2 f0 = unpack2(acc[0]), f1 = unpack2(acc[1]);
            float2 f2 = unpack2(acc[2]), f3 = unpack2(acc[3]);
            float4* dst = (float4*)&s_sh[q][u * 8];
            dst[0] = make_float4(f0.x, f0.y, f1.x, f1.y);
            dst[1] = make_float4(f2.x, f2.y, f3.x, f3.y);
        }
        __syncthreads();

        // y_t for 4 batches (half selected by bs)
        unsigned long long ya[2] = {0ull, 0ull};
#pragma unroll
        for (int k = 0; k < U_; k++) {
            const unsigned long long cv = dup2(cy_sh[k * NOUT + o]);
            const ulonglong2 sp = *(const ulonglong2*)&s_sh[q][k * 8 + bs * 4];
            ya[0] = ffma2(sp.x, cv, ya[0]);
            ya[1] = ffma2(sp.y, cv, ya[1]);
        }
        {
            float2 y0 = unpack2(ya[0]), y1 = unpack2(ya[1]);
            const int bb = b0 + bs * 4;
            y[((size_t)(bb + 0) * T_ + t) * NOUT + o] = y0.x;
            y[((size_t)(bb + 1) * T_ + t) * NOUT + o] = y0.y;
            y[((size_t)(bb + 2) * T_ + t) * NOUT + o] = y1.x;
            y[((size_t)(bb + 3) * T_ + t) * NOUT + o] = y1.y;
        }

        p = q;
#pragma unroll
        for (int j = 0; j < 8; j++) kyc[j] = kyn[j];
    }

#pragma unroll
    for (int j = 0; j < 8; j++)
        g_E[((size_t)(b0 + j) * CCH + c) * U_ + u] = s_sh[p][u * 8 + j];
}

// ---------------------------------------------------------------------------
// K4: matsq  O = A @ A
// ---------------------------------------------------------------------------
__global__ __launch_bounds__(128) void matsq(const float* __restrict__ A,
                                             float* __restrict__ O) {
    const int r = blockIdx.x, u = threadIdx.x;
    __shared__ float row[U_];
    row[u] = A[r * U_ + u];
    __syncthreads();
    float a0 = 0.f, a1 = 0.f, a2 = 0.f, a3 = 0.f;
#pragma unroll
    for (int k = 0; k < U_; k += 4) {
        a0 = fmaf(row[k + 0], A[(k + 0) * U_ + u], a0);
        a1 = fmaf(row[k + 1], A[(k + 1) * U_ + u], a1);
        a2 = fmaf(row[k + 2], A[(k + 2) * U_ + u], a2);
        a3 = fmaf(row[k + 3], A[(k + 3) * U_ + u], a3);
    }
    O[r * U_ + u] = (a0 + a1) + (a2 + a3);
}

// ---------------------------------------------------------------------------
// K5: carry scan. carry[b,0]=0; carry[b,c] = E[b,c-1] + carry[b,c-1]@A64
// ---------------------------------------------------------------------------
__global__ __launch_bounds__(128) void pass2_kernel() {
    const int b = blockIdx.x, u = threadIdx.x;
    __shared__ float ss[2][U_];
    float m[U_];
#pragma unroll
    for (int k = 0; k < U_; k++) m[k] = g_A64[k * U_ + u];

    float su = 0.f;
    float e = g_E[((size_t)b * CCH) * U_ + u];
    ss[0][u] = 0.f;
    __syncthreads();

    int p = 0;
#pragma unroll 1
    for (int c = 0; c < CCH; c++) {
        g_carry[((size_t)b * CCH + c) * U_ + u] = su;
        float a0 = e, a1 = 0.f, a2 = 0.f, a3 = 0.f;
        if (c < CCH - 1) e = g_E[((size_t)b * CCH + c + 1) * U_ + u];
#pragma unroll
        for (int k = 0; k < U_; k += 4) {
            a0 = fmaf(ss[p][k + 0], m[k + 0], a0);
            a1 = fmaf(ss[p][k + 1], m[k + 1], a1);
            a2 = fmaf(ss[p][k + 2], m[k + 2], a2);
            a3 = fmaf(ss[p][k + 3], m[k + 3], a3);
        }
        su = (a0 + a1) + (a2 + a3);
        ss[p ^ 1][u] = su;
        __syncthreads();
        p ^= 1;
    }
}

// ---------------------------------------------------------------------------
// K6: wbuild. CTA s computes W[s] = A^(s+1) @ CyT via binary power chain.
// 512 threads, 64KB dynamic smem (double-buffered V).
// ---------------------------------------------------------------------------
__global__ __launch_bounds__(512) void wbuild(const float* __restrict__ A1,
                                              const float* __restrict__ CyT) {
    extern __shared__ float V[];                 // 2 x 8192 floats
    float* cur = V;
    float* nxt = V + 8192;
    const int s = blockIdx.x;
    const int n = s + 1;
    const int tid = threadIdx.x;
    const int o = tid & 63, kg = tid >> 6;       // 8 k-groups of 16

    for (int i = tid; i < U_ * NOUT; i += 512) cur[i] = CyT[i];
    __syncthreads();

#pragma unroll 1
    for (int b = 0; b < 7; b++) {
        if (!((n >> b) & 1)) continue;
        const float* P = (b == 0) ? A1
                       : (b == 1) ? g_A2  : (b == 2) ? g_A4
                       : (b == 3) ? g_A8  : (b == 4) ? g_A16
                       : (b == 5) ? g_A32 : g_A64;
#pragma unroll 1
        for (int i = 0; i < 16; i++) {
            const int k = kg * 16 + i;
            float a0 = 0.f, a1 = 0.f, a2 = 0.f, a3 = 0.f;
#pragma unroll
            for (int m = 0; m < U_; m += 4) {
                a0 = fmaf(P[k * U_ + m + 0], cur[(m + 0) * 64 + o], a0);
                a1 = fmaf(P[k * U_ + m + 1], cur[(m + 1) * 64 + o], a1);
                a2 = fmaf(P[k * U_ + m + 2], cur[(m + 2) * 64 + o], a2);
                a3 = fmaf(P[k * U_ + m + 3], cur[(m + 3) * 64 + o], a3);
            }
            nxt[k * 64 + o] = (a0 + a1) + (a2 + a3);
        }
        __syncthreads();
        float* tmp = cur; cur = nxt; nxt = tmp;
    }

#pragma unroll 1
    for (int i = 0; i < 16; i++) {
        const int k = kg * 16 + i;
        g_Wt[(size_t)k * (LCH * NOUT) + s * 64 + o] = cur[k * 64 + o];
    }
}

// ---------------------------------------------------------------------------
// K7: fixup  y += carry @ Wt   (M=4096 (b,c), N=4096 (step,o), K=128)
// ---------------------------------------------------------------------------
__global__ __launch_bounds__(128, 2) void fixup(float* __restrict__ y) {
    const int nt = blockIdx.x, mt = blockIdx.y;
    const int tid = threadIdx.x;
    __shared__ __align__(16) float As[U_ * 64];
    __shared__ __align__(16) float Bs[U_ * 32];

    {
        const int mi = tid >> 1, kh = (tid & 1) * 64;
        const float* src = &g_carry[((size_t)(mt * 64 + mi)) * U_ + kh];
#pragma unroll
        for (int i = 0; i < 64; i += 4) {
            float4 v = *(const float4*)(src + i);
            As[(kh + i + 0) * 64 + mi] = v.x;
            As[(kh + i + 1) * 64 + mi] = v.y;
            As[(kh + i + 2) * 64 + mi] = v.z;
            As[(kh + i + 3) * 64 + mi] = v.w;
        }
    }
    {
        const float4* src = (const float4*)&g_Wt[(size_t)tid * (LCH * NOUT) + nt * 32];
        float4* dst = (float4*)&Bs[tid * 32];
#pragma unroll
        for (int i = 0; i < 8; i++) dst[i] = src[i];
    }
    __syncthreads();

    const int ni = tid & 7, mi = tid >> 3;
    const int n4 = ni * 4, m4 = mi * 4;

    unsigned long long acc[4][2];
#pragma unroll
    for (int i = 0; i < 4; i++) { acc[i][0] = 0ull; acc[i][1] = 0ull; }

#pragma unroll 8
    for (int k = 0; k < U_; k++) {
        const float4 a = *(const float4*)&As[k * 64 + m4];
        const ulonglong2 b = *(const ulonglong2*)&Bs[k * 32 + n4];
        const unsigned long long a0 = dup2(a.x), a1 = dup2(a.y);
        const unsigned long long a2 = dup2(a.z), a3 = dup2(a.w);
        acc[0][0] = ffma2(b.x, a0, acc[0][0]);
        acc[0][1] = ffma2(b.y, a0, acc[0][1]);
        acc[1][0] = ffma2(b.x, a1, acc[1][0]);
        acc[1][1] = ffma2(b.y, a1, acc[1][1]);
        acc[2][0] = ffma2(b.x, a2, acc[2][0]);
        acc[2][1] = ffma2(b.y, a2, acc[2][1]);
        acc[3][0] = ffma2(b.x, a3, acc[3][0]);
        acc[3][1] = ffma2(b.y, a3, acc[3][1]);
    }

#pragma unroll
    for (int i = 0; i < 4; i++) {
        const int r = mt * 64 + m4 + i;
        float* yp = y + (size_t)r * 4096 + nt * 32 + n4;
        float4 e0 = *(float4*)yp;
        float2 f0 = unpack2(acc[i][0]), f1 = unpack2(acc[i][1]);
        e0.x += f0.x; e0.y += f0.y; e0.z += f1.x; e0.w += f1.y;
        *(float4*)yp = e0;
    }
}

// ---------------------------------------------------------------------------
// Launch. scan occupies positions 3, 4, 7 (profiler lands on one of these).
// ---------------------------------------------------------------------------
extern "C" void kernel_launch(void* const* d_in, const int* in_sizes, int n_in,
                              void* d_out, int out_size) {
    const float* x   = (const float*)d_in[0];
    const float* AT  = (const float*)d_in[1];
    const float* KT  = (const float*)d_in[2];
    const float* CyT = (const float*)d_in[3];
    float* y = (float*)d_out;

    float *A2, *A4, *A8, *A16, *A32, *A64;
    cudaGetSymbolAddress((void**)&A2,  g_A2);
    cudaGetSymbolAddress((void**)&A4,  g_A4);
    cudaGetSymbolAddress((void**)&A8,  g_A8);
    cudaGetSymbolAddress((void**)&A16, g_A16);
    cudaGetSymbolAddress((void**)&A32, g_A32);
    cudaGetSymbolAddress((void**)&A64, g_A64);

    cudaFuncSetAttribute(wbuild, cudaFuncAttributeMaxDynamicSharedMemorySize, 65536);

    ky_kernel<<<(B_ * T_) / 256, 128>>>(x, KT);             // 1
    transA_kernel<<<U_, U_>>>(AT);                          // 2
    scan_kernel<<<dim3(CCH, 3), 128>>>(CyT, y, 0);          // 3  <- ncu candidate
    scan_kernel<<<dim3(CCH, 3), 128>>>(CyT, y, 3);          // 4  <- ncu candidate
    matsq<<<128, 128>>>(AT,  A2);                           // 5
    matsq<<<128, 128>>>(A2,  A4);                           // 6
    scan_kernel<<<dim3(CCH, 2), 128>>>(CyT, y, 6);          // 7  <- ncu candidate
    matsq<<<128, 128>>>(A4,  A8);                           // 8
    matsq<<<128, 128>>>(A8,  A16);                          // 9
    matsq<<<128, 128>>>(A16, A32);                          // 10
    matsq<<<128, 128>>>(A32, A64);                          // 11
    pass2_kernel<<<B_, 128>>>();                            // 12
    wbuild<<<LCH, 512, 65536>>>(AT, CyT);                   // 13
    fixup<<<dim3(128, 64), 128>>>(y);                       // 14
}

// round 5
// speedup vs baseline: 1.5487x; 1.5487x over previous
#include <cuda_runtime.h>
#include <cstdint>

#define B_   64
#define T_   4096
#define NIN  64
#define U_   128
#define NOUT 64
#define CCH  64
#define LCH  64

// ---------------------------------------------------------------------------
// Static device scratch
// ---------------------------------------------------------------------------
__device__ float g_Ky[B_ * T_ * U_];      // 128 MB : Ky[b][t][u]
__device__ float g_S[B_ * T_ * U_];       // 128 MB : chunk-local states s[b][t][u]
__device__ float g_carry[B_ * CCH * U_];
__device__ float g_A2[U_ * U_], g_A4[U_ * U_], g_A8[U_ * U_];
__device__ float g_A16[U_ * U_], g_A32[U_ * U_], g_A64[U_ * U_];
__device__ float g_Wt[U_ * LCH * NOUT];   // [k][step][o]; W[s] = A^(s+1)@CyT

// ---------------------------------------------------------------------------
// Packed f32x2 helpers
// ---------------------------------------------------------------------------
__device__ __forceinline__ unsigned long long ffma2(unsigned long long a,
                                                    unsigned long long b,
                                                    unsigned long long c) {
    unsigned long long d;
    asm("fma.rn.f32x2 %0, %1, %2, %3;" : "=l"(d) : "l"(a), "l"(b), "l"(c));
    return d;
}
__device__ __forceinline__ unsigned long long dup2(float v) {
    unsigned long long r;
    asm("mov.b64 %0, {%1, %1};" : "=l"(r) : "f"(v));
    return r;
}
__device__ __forceinline__ unsigned long long pack2(float x, float y) {
    unsigned long long r;
    asm("mov.b64 %0, {%1, %2};" : "=l"(r) : "f"(x), "f"(y));
    return r;
}
__device__ __forceinline__ float2 unpack2(unsigned long long v) {
    float2 f;
    asm("mov.b64 {%0, %1}, %2;" : "=f"(f.x), "=f"(f.y) : "l"(v));
    return f;
}

// 8m x 4n register-tile MAC step (verified in R3 k8a/k8b)
template <int BSTRIDE>
__device__ __forceinline__ void mma8x4(unsigned long long acc[4][4],
                                       const float* __restrict__ As,
                                       const float* __restrict__ Bs,
                                       int k, int m0, int n4) {
    const ulonglong2 a01 = *(const ulonglong2*)&As[k * 64 + m0];
    const ulonglong2 a23 = *(const ulonglong2*)&As[k * 64 + m0 + 4];
    const float4 bv = *(const float4*)&Bs[k * BSTRIDE + n4];
    const unsigned long long b0 = dup2(bv.x), b1 = dup2(bv.y);
    const unsigned long long b2 = dup2(bv.z), b3 = dup2(bv.w);
    acc[0][0] = ffma2(a01.x, b0, acc[0][0]);
    acc[0][1] = ffma2(a01.x, b1, acc[0][1]);
    acc[0][2] = ffma2(a01.x, b2, acc[0][2]);
    acc[0][3] = ffma2(a01.x, b3, acc[0][3]);
    acc[1][0] = ffma2(a01.y, b0, acc[1][0]);
    acc[1][1] = ffma2(a01.y, b1, acc[1][1]);
    acc[1][2] = ffma2(a01.y, b2, acc[1][2]);
    acc[1][3] = ffma2(a01.y, b3, acc[1][3]);
    acc[2][0] = ffma2(a23.x, b0, acc[2][0]);
    acc[2][1] = ffma2(a23.x, b1, acc[2][1]);
    acc[2][2] = ffma2(a23.x, b2, acc[2][2]);
    acc[2][3] = ffma2(a23.x, b3, acc[2][3]);
    acc[3][0] = ffma2(a23.y, b0, acc[3][0]);
    acc[3][1] = ffma2(a23.y, b1, acc[3][1]);
    acc[3][2] = ffma2(a23.y, b2, acc[3][2]);
    acc[3][3] = ffma2(a23.y, b3, acc[3][3]);
}

// ---------------------------------------------------------------------------
// K1: Ky = x @ KT  (proven R1 kernel)
// ---------------------------------------------------------------------------
__global__ __launch_bounds__(128) void ky_kernel(const float* __restrict__ x,
                                                 const float* __restrict__ KT) {
    const int u = threadIdx.x;
    float kt[NIN];
#pragma unroll
    for (int n = 0; n < NIN; n++) kt[n] = KT[n * U_ + u];

    __shared__ __align__(16) float xs[NIN * 8];
    const int row0 = blockIdx.x * 256;

#pragma unroll 1
    for (int tile = 0; tile < 32; tile++) {
        const int r0 = row0 + tile * 8;
        float4 xv = reinterpret_cast<const float4*>(x + (size_t)r0 * NIN)[u];
        __syncthreads();
        {
            const int rr = u >> 4;
            const int n0 = (u & 15) * 4;
            xs[(n0 + 0) * 8 + rr] = xv.x;
            xs[(n0 + 1) * 8 + rr] = xv.y;
            xs[(n0 + 2) * 8 + rr] = xv.z;
            xs[(n0 + 3) * 8 + rr] = xv.w;
        }
        __syncthreads();

        unsigned long long acc[4] = {0ull, 0ull, 0ull, 0ull};
#pragma unroll
        for (int n = 0; n < NIN; n++) {
            unsigned long long kv = dup2(kt[n]);
            ulonglong2 a = *reinterpret_cast<const ulonglong2*>(&xs[n * 8]);
            ulonglong2 b = *reinterpret_cast<const ulonglong2*>(&xs[n * 8 + 4]);
            acc[0] = ffma2(a.x, kv, acc[0]);
            acc[1] = ffma2(a.y, kv, acc[1]);
            acc[2] = ffma2(b.x, kv, acc[2]);
            acc[3] = ffma2(b.y, kv, acc[3]);
        }
#pragma unroll
        for (int i = 0; i < 4; i++) {
            float2 f = unpack2(acc[i]);
            g_Ky[(size_t)(r0 + 2 * i)     * U_ + u] = f.x;
            g_Ky[(size_t)(r0 + 2 * i + 1) * U_ + u] = f.y;
        }
    }
}

// ---------------------------------------------------------------------------
// K2: matsq  O = A @ A
// ---------------------------------------------------------------------------
__global__ __launch_bounds__(128) void matsq(const float* __restrict__ A,
                                             float* __restrict__ O) {
    const int r = blockIdx.x, u = threadIdx.x;
    __shared__ float row[U_];
    row[u] = A[r * U_ + u];
    __syncthreads();
    float a0 = 0.f, a1 = 0.f, a2 = 0.f, a3 = 0.f;
#pragma unroll
    for (int k = 0; k < U_; k += 4) {
        a0 = fmaf(row[k + 0], A[(k + 0) * U_ + u], a0);
        a1 = fmaf(row[k + 1], A[(k + 1) * U_ + u], a1);
        a2 = fmaf(row[k + 2], A[(k + 2) * U_ + u], a2);
        a3 = fmaf(row[k + 3], A[(k + 3) * U_ + u], a3);
    }
    O[r * U_ + u] = (a0 + a1) + (a2 + a3);
}

// ---------------------------------------------------------------------------
// K3: scan.  s_{t+1}[u] = ky_t[u] + sum_k s_t[k]*AT[k][u], chunk-local (zero
// init), writes every state to g_S.  A column in registers, 8 batches/CTA.
// 512 CTAs one launch; occ 3 target.
// ---------------------------------------------------------------------------
__global__ __launch_bounds__(128, 3) void scan_kernel(const float* __restrict__ AT) {
    const int c = blockIdx.x, bg = blockIdx.y, u = threadIdx.x;
    const int b0 = bg * 8;

    __shared__ __align__(16) float s_sh[2][U_ * 8];   // 8 KB

    float at[U_];
#pragma unroll
    for (int k = 0; k < U_; k++) at[k] = AT[k * U_ + u];   // coalesced per k

#pragma unroll
    for (int j = 0; j < 8; j++) s_sh[0][u * 8 + j] = 0.f;
    __syncthreads();

    float kyc[8];
#pragma unroll
    for (int j = 0; j < 8; j++)
        kyc[j] = g_Ky[((size_t)(b0 + j) * T_ + c * LCH) * U_ + u];

    int p = 0;
#pragma unroll 1
    for (int step = 0; step < LCH; step++) {
        const int t = c * LCH + step;

        float kyn[8];
        if (step < LCH - 1) {
#pragma unroll
            for (int j = 0; j < 8; j++)
                kyn[j] = g_Ky[((size_t)(b0 + j) * T_ + t + 1) * U_ + u];
        } else {
#pragma unroll
            for (int j = 0; j < 8; j++) kyn[j] = 0.f;
        }

        unsigned long long acc[4];
#pragma unroll
        for (int i = 0; i < 4; i++) acc[i] = pack2(kyc[2 * i], kyc[2 * i + 1]);

#pragma unroll
        for (int k = 0; k < U_; k++) {
            const unsigned long long av = dup2(at[k]);
            const ulonglong2 s01 = *(const ulonglong2*)&s_sh[p][k * 8];
            const ulonglong2 s23 = *(const ulonglong2*)&s_sh[p][k * 8 + 4];
            acc[0] = ffma2(s01.x, av, acc[0]);
            acc[1] = ffma2(s01.y, av, acc[1]);
            acc[2] = ffma2(s23.x, av, acc[2]);
            acc[3] = ffma2(s23.y, av, acc[3]);
        }

        const int q = p ^ 1;
        float2 f0 = unpack2(acc[0]), f1 = unpack2(acc[1]);
        float2 f2 = unpack2(acc[2]), f3 = unpack2(acc[3]);
        {
            float4* dst = (float4*)&s_sh[q][u * 8];
            dst[0] = make_float4(f0.x, f0.y, f1.x, f1.y);
            dst[1] = make_float4(f2.x, f2.y, f3.x, f3.y);
        }
        // coalesced state store (u-major)
        g_S[((size_t)(b0 + 0) * T_ + t) * U_ + u] = f0.x;
        g_S[((size_t)(b0 + 1) * T_ + t) * U_ + u] = f0.y;
        g_S[((size_t)(b0 + 2) * T_ + t) * U_ + u] = f1.x;
        g_S[((size_t)(b0 + 3) * T_ + t) * U_ + u] = f1.y;
        g_S[((size_t)(b0 + 4) * T_ + t) * U_ + u] = f2.x;
        g_S[((size_t)(b0 + 5) * T_ + t) * U_ + u] = f2.y;
        g_S[((size_t)(b0 + 6) * T_ + t) * U_ + u] = f3.x;
        g_S[((size_t)(b0 + 7) * T_ + t) * U_ + u] = f3.y;
        __syncthreads();

        p = q;
#pragma unroll
        for (int j = 0; j < 8; j++) kyc[j] = kyn[j];
    }
}

// ---------------------------------------------------------------------------
// K4: ygemm  y = S @ CyT   (262144 x 64, K=128).  64 rows/CTA, 64KB dyn smem.
// ---------------------------------------------------------------------------
__global__ __launch_bounds__(128) void ygemm(const float* __restrict__ CyT,
                                             float* __restrict__ y) {
    extern __shared__ float sm[];
    float* As = sm;           // [128][64]
    float* Bs = sm + 8192;    // [128][64]
    const int tid = threadIdx.x;
    const int row0 = blockIdx.x * 64;

    {   // stage S tile transposed
        const int mi = tid >> 1, kh = (tid & 1) * 64;
        const float* src = g_S + (size_t)(row0 + mi) * U_ + kh;
#pragma unroll
        for (int j = 0; j < 64; j += 4) {
            float4 v = *(const float4*)(src + j);
            As[(kh + j + 0) * 64 + mi] = v.x;
            As[(kh + j + 1) * 64 + mi] = v.y;
            As[(kh + j + 2) * 64 + mi] = v.z;
            As[(kh + j + 3) * 64 + mi] = v.w;
        }
    }
    {   // stage CyT
        const float4* src = (const float4*)CyT + (size_t)tid * 16;
        float4* dst = (float4*)(Bs + tid * 64);
#pragma unroll
        for (int j = 0; j < 16; j++) dst[j] = src[j];
    }
    __syncthreads();

    const int ni = tid & 15, mg = tid >> 4;
    const int n4 = ni * 4, m0 = mg * 8;
    unsigned long long acc[4][4] = {};
#pragma unroll 16
    for (int k = 0; k < U_; k++) mma8x4<64>(acc, As, Bs, k, m0, n4);

#pragma unroll
    for (int p = 0; p < 4; p++) {
        float2 q0 = unpack2(acc[p][0]), q1 = unpack2(acc[p][1]);
        float2 q2 = unpack2(acc[p][2]), q3 = unpack2(acc[p][3]);
        const int r = row0 + m0 + 2 * p;
        *(float4*)(y + (size_t)r * NOUT + n4) =
            make_float4(q0.x, q1.x, q2.x, q3.x);
        *(float4*)(y + (size_t)(r + 1) * NOUT + n4) =
            make_float4(q0.y, q1.y, q2.y, q3.y);
    }
}

// ---------------------------------------------------------------------------
// K5: carry scan.  carry[b,0]=0; carry[b,c] = E[b,c-1] + carry[b,c-1]@A64
// E[b,c] = g_S[b][c*64+63]
// ---------------------------------------------------------------------------
__global__ __launch_bounds__(128) void pass2_kernel() {
    const int b = blockIdx.x, u = threadIdx.x;
    __shared__ float ss[2][U_];
    float m[U_];
#pragma unroll
    for (int k = 0; k < U_; k++) m[k] = g_A64[k * U_ + u];

    float su = 0.f;
    float e = g_S[((size_t)b * T_ + (LCH - 1)) * U_ + u];
    ss[0][u] = 0.f;
    __syncthreads();

    int p = 0;
#pragma unroll 1
    for (int c = 0; c < CCH; c++) {
        g_carry[((size_t)b * CCH + c) * U_ + u] = su;
        float a0 = e, a1 = 0.f, a2 = 0.f, a3 = 0.f;
        if (c < CCH - 1)
            e = g_S[((size_t)b * T_ + (c + 1) * LCH + (LCH - 1)) * U_ + u];
#pragma unroll
        for (int k = 0; k < U_; k += 4) {
            a0 = fmaf(ss[p][k + 0], m[k + 0], a0);
            a1 = fmaf(ss[p][k + 1], m[k + 1], a1);
            a2 = fmaf(ss[p][k + 2], m[k + 2], a2);
            a3 = fmaf(ss[p][k + 3], m[k + 3], a3);
        }
        su = (a0 + a1) + (a2 + a3);
        ss[p ^ 1][u] = su;
        __syncthreads();
        p ^= 1;
    }
}

// ---------------------------------------------------------------------------
// K6: wbuild. CTA s: W[s] = A^(s+1) @ CyT (binary power chain). 64KB dyn smem.
// ---------------------------------------------------------------------------
__global__ __launch_bounds__(512) void wbuild(const float* __restrict__ A1,
                                              const float* __restrict__ CyT) {
    extern __shared__ float V[];
    float* cur = V;
    float* nxt = V + 8192;
    const int s = blockIdx.x;
    const int n = s + 1;
    const int tid = threadIdx.x;
    const int o = tid & 63, kg = tid >> 6;

    for (int i = tid; i < U_ * NOUT; i += 512) cur[i] = CyT[i];
    __syncthreads();

#pragma unroll 1
    for (int b = 0; b < 7; b++) {
        if (!((n >> b) & 1)) continue;
        const float* P = (b == 0) ? A1
                       : (b == 1) ? g_A2  : (b == 2) ? g_A4
                       : (b == 3) ? g_A8  : (b == 4) ? g_A16
                       : (b == 5) ? g_A32 : g_A64;
#pragma unroll 1
        for (int i = 0; i < 16; i++) {
            const int k = kg * 16 + i;
            float a0 = 0.f, a1 = 0.f, a2 = 0.f, a3 = 0.f;
#pragma unroll
            for (int m = 0; m < U_; m += 4) {
                a0 = fmaf(P[k * U_ + m + 0], cur[(m + 0) * 64 + o], a0);
                a1 = fmaf(P[k * U_ + m + 1], cur[(m + 1) * 64 + o], a1);
                a2 = fmaf(P[k * U_ + m + 2], cur[(m + 2) * 64 + o], a2);
                a3 = fmaf(P[k * U_ + m + 3], cur[(m + 3) * 64 + o], a3);
            }
            nxt[k * 64 + o] = (a0 + a1) + (a2 + a3);
        }
        __syncthreads();
        float* tmp = cur; cur = nxt; nxt = tmp;
    }

#pragma unroll 1
    for (int i = 0; i < 16; i++) {
        const int k = kg * 16 + i;
        g_Wt[(size_t)k * (LCH * NOUT) + s * 64 + o] = cur[k * 64 + o];
    }
}

// ---------------------------------------------------------------------------
// K7: fixup  y += carry @ Wt   (M=4096 (b,c), N=4096 (step,o), K=128)
// ---------------------------------------------------------------------------
__global__ __launch_bounds__(128, 2) void fixup(float* __restrict__ y) {
    const int nt = blockIdx.x, mt = blockIdx.y;
    const int tid = threadIdx.x;
    __shared__ __align__(16) float As[U_ * 64];
    __shared__ __align__(16) float Bs[U_ * 32];

    {
        const int mi = tid >> 1, kh = (tid & 1) * 64;
        const float* src = &g_carry[((size_t)(mt * 64 + mi)) * U_ + kh];
#pragma unroll
        for (int i = 0; i < 64; i += 4) {
            float4 v = *(const float4*)(src + i);
            As[(kh + i + 0) * 64 + mi] = v.x;
            As[(kh + i + 1) * 64 + mi] = v.y;
            As[(kh + i + 2) * 64 + mi] = v.z;
            As[(kh + i + 3) * 64 + mi] = v.w;
        }
    }
    {
        const float4* src = (const float4*)&g_Wt[(size_t)tid * (LCH * NOUT) + nt * 32];
        float4* dst = (float4*)&Bs[tid * 32];
#pragma unroll
        for (int i = 0; i < 8; i++) dst[i] = src[i];
    }
    __syncthreads();

    const int ni = tid & 7, mi = tid >> 3;
    const int n4 = ni * 4, m4 = mi * 4;

    unsigned long long acc[4][2];
#pragma unroll
    for (int i = 0; i < 4; i++) { acc[i][0] = 0ull; acc[i][1] = 0ull; }

#pragma unroll 8
    for (int k = 0; k < U_; k++) {
        const float4 a = *(const float4*)&As[k * 64 + m4];
        const ulonglong2 b = *(const ulonglong2*)&Bs[k * 32 + n4];
        const unsigned long long a0 = dup2(a.x), a1 = dup2(a.y);
        const unsigned long long a2 = dup2(a.z), a3 = dup2(a.w);
        acc[0][0] = ffma2(b.x, a0, acc[0][0]);
        acc[0][1] = ffma2(b.y, a0, acc[0][1]);
        acc[1][0] = ffma2(b.x, a1, acc[1][0]);
        acc[1][1] = ffma2(b.y, a1, acc[1][1]);
        acc[2][0] = ffma2(b.x, a2, acc[2][0]);
        acc[2][1] = ffma2(b.y, a2, acc[2][1]);
        acc[3][0] = ffma2(b.x, a3, acc[3][0]);
        acc[3][1] = ffma2(b.y, a3, acc[3][1]);
    }

#pragma unroll
    for (int i = 0; i < 4; i++) {
        const int r = mt * 64 + m4 + i;
        float* yp = y + (size_t)r * 4096 + nt * 32 + n4;
        float4 e0 = *(float4*)yp;
        float2 f0 = unpack2(acc[i][0]), f1 = unpack2(acc[i][1]);
        e0.x += f0.x; e0.y += f0.y; e0.z += f1.x; e0.w += f1.y;
        *(float4*)yp = e0;
    }
}

// ---------------------------------------------------------------------------
// Launch.  #3 = scan, #4 = ygemm (profiler lands on one of these).
// ---------------------------------------------------------------------------
extern "C" void kernel_launch(void* const* d_in, const int* in_sizes, int n_in,
                              void* d_out, int out_size) {
    const float* x   = (const float*)d_in[0];
    const float* AT  = (const float*)d_in[1];
    const float* KT  = (const float*)d_in[2];
    const float* CyT = (const float*)d_in[3];
    float* y = (float*)d_out;

    float *A2, *A4, *A8, *A16, *A32, *A64;
    cudaGetSymbolAddress((void**)&A2,  g_A2);
    cudaGetSymbolAddress((void**)&A4,  g_A4);
    cudaGetSymbolAddress((void**)&A8,  g_A8);
    cudaGetSymbolAddress((void**)&A16, g_A16);
    cudaGetSymbolAddress((void**)&A32, g_A32);
    cudaGetSymbolAddress((void**)&A64, g_A64);

    cudaFuncSetAttribute(ygemm,  cudaFuncAttributeMaxDynamicSharedMemorySize, 65536);
    cudaFuncSetAttribute(wbuild, cudaFuncAttributeMaxDynamicSharedMemorySize, 65536);

    ky_kernel<<<(B_ * T_) / 256, 128>>>(x, KT);           // 1
    matsq<<<128, 128>>>(AT, A2);                          // 2
    scan_kernel<<<dim3(CCH, 8), 128>>>(AT);               // 3  <- ncu candidate
    ygemm<<<(B_ * T_) / 64, 128, 65536>>>(CyT, y);        // 4  <- ncu candidate
    matsq<<<128, 128>>>(A2,  A4);                         // 5
    matsq<<<128, 128>>>(A4,  A8);                         // 6
    matsq<<<128, 128>>>(A8,  A16);                        // 7
    matsq<<<128, 128>>>(A16, A32);                        // 8
    matsq<<<128, 128>>>(A32, A64);                        // 9
    pass2_kernel<<<B_, 128>>>();                          // 10
    wbuild<<<LCH, 512, 65536>>>(AT, CyT);                 // 11
    fixup<<<dim3(128, 64), 128>>>(y);                     // 12
}

// round 6
// speedup vs baseline: 1.7138x; 1.1066x over previous
#include <cuda_runtime.h>
#include <cstdint>

#define B_   64
#define T_   4096
#define NIN  64
#define U_   128
#define NOUT 64
#define CCH  64     // chunks (per batch)
#define LCH  64     // timesteps per chunk
#define HT   2048   // T/2 : odd-state (pair) count per batch
#define HCH  32     // odd states per chunk

// ---------------------------------------------------------------------------
// Static device scratch
// ---------------------------------------------------------------------------
__device__ float g_Z[B_ * HT * U_];       // 64 MB : Z_i = ky[2i+1] + ky[2i]@A
__device__ float g_S[B_ * HT * U_];       // 64 MB : chunk-local odd states e_i
__device__ float g_carry[B_ * CCH * U_];
__device__ float g_M[U_ * U_];            // stacked [[KT@A],[KT]]
__device__ float g_KC[NIN * NOUT];        // KT@CyT   [64,64]
__device__ float g_ACyT[U_ * NOUT];       // A@CyT    [128,64]
__device__ float g_A2[U_ * U_], g_A4[U_ * U_], g_A8[U_ * U_];
__device__ float g_A16[U_ * U_], g_A32[U_ * U_], g_A64[U_ * U_];
__device__ float g_Wt[U_ * LCH * NOUT];   // [k][step*64+o]; W[s] = A^(s+1)@CyT

// ---------------------------------------------------------------------------
// Packed f32x2 helpers
// ---------------------------------------------------------------------------
__device__ __forceinline__ unsigned long long ffma2(unsigned long long a,
                                                    unsigned long long b,
                                                    unsigned long long c) {
    unsigned long long d;
    asm("fma.rn.f32x2 %0, %1, %2, %3;" : "=l"(d) : "l"(a), "l"(b), "l"(c));
    return d;
}
__device__ __forceinline__ unsigned long long dup2(float v) {
    unsigned long long r;
    asm("mov.b64 %0, {%1, %1};" : "=l"(r) : "f"(v));
    return r;
}
__device__ __forceinline__ unsigned long long pack2(float x, float y) {
    unsigned long long r;
    asm("mov.b64 %0, {%1, %2};" : "=l"(r) : "f"(x), "f"(y));
    return r;
}
__device__ __forceinline__ float2 unpack2(unsigned long long v) {
    float2 f;
    asm("mov.b64 {%0, %1}, %2;" : "=f"(f.x), "=f"(f.y) : "l"(v));
    return f;
}

// 8m x 4n register-tile MAC step (verified R3/R5)
template <int BSTRIDE>
__device__ __forceinline__ void mma8x4(unsigned long long acc[4][4],
                                       const float* __restrict__ As,
                                       const float* __restrict__ Bs,
                                       int k, int m0, int n4) {
    const ulonglong2 a01 = *(const ulonglong2*)&As[k * 64 + m0];
    const ulonglong2 a23 = *(const ulonglong2*)&As[k * 64 + m0 + 4];
    const float4 bv = *(const float4*)&Bs[k * BSTRIDE + n4];
    const unsigned long long b0 = dup2(bv.x), b1 = dup2(bv.y);
    const unsigned long long b2 = dup2(bv.z), b3 = dup2(bv.w);
    acc[0][0] = ffma2(a01.x, b0, acc[0][0]);
    acc[0][1] = ffma2(a01.x, b1, acc[0][1]);
    acc[0][2] = ffma2(a01.x, b2, acc[0][2]);
    acc[0][3] = ffma2(a01.x, b3, acc[0][3]);
    acc[1][0] = ffma2(a01.y, b0, acc[1][0]);
    acc[1][1] = ffma2(a01.y, b1, acc[1][1]);
    acc[1][2] = ffma2(a01.y, b2, acc[1][2]);
    acc[1][3] = ffma2(a01.y, b3, acc[1][3]);
    acc[2][0] = ffma2(a23.x, b0, acc[2][0]);
    acc[2][1] = ffma2(a23.x, b1, acc[2][1]);
    acc[2][2] = ffma2(a23.x, b2, acc[2][2]);
    acc[2][3] = ffma2(a23.x, b3, acc[2][3]);
    acc[3][0] = ffma2(a23.y, b0, acc[3][0]);
    acc[3][1] = ffma2(a23.y, b1, acc[3][1]);
    acc[3][2] = ffma2(a23.y, b2, acc[3][2]);
    acc[3][3] = ffma2(a23.y, b3, acc[3][3]);
}

// ---------------------------------------------------------------------------
// K-A: matsq  O = A @ A
// ---------------------------------------------------------------------------
__global__ __launch_bounds__(128) void matsq(const float* __restrict__ A,
                                             float* __restrict__ O) {
    const int r = blockIdx.x, u = threadIdx.x;
    __shared__ float row[U_];
    row[u] = A[r * U_ + u];
    __syncthreads();
    float a0 = 0.f, a1 = 0.f, a2 = 0.f, a3 = 0.f;
#pragma unroll
    for (int k = 0; k < U_; k += 4) {
        a0 = fmaf(row[k + 0], A[(k + 0) * U_ + u], a0);
        a1 = fmaf(row[k + 1], A[(k + 1) * U_ + u], a1);
        a2 = fmaf(row[k + 2], A[(k + 2) * U_ + u], a2);
        a3 = fmaf(row[k + 3], A[(k + 3) * U_ + u], a3);
    }
    O[r * U_ + u] = (a0 + a1) + (a2 + a3);
}

// ---------------------------------------------------------------------------
// K-B: buildM.  M[0:64] = KT@A (row r), M[64:128] = KT (copy).
// ---------------------------------------------------------------------------
__global__ __launch_bounds__(128) void buildM(const float* __restrict__ KT,
                                              const float* __restrict__ A) {
    const int r = blockIdx.x, u = threadIdx.x;
    __shared__ float row[U_];
    row[u] = KT[r * U_ + u];
    __syncthreads();
    float a0 = 0.f, a1 = 0.f, a2 = 0.f, a3 = 0.f;
#pragma unroll
    for (int k = 0; k < U_; k += 4) {
        a0 = fmaf(row[k + 0], A[(k + 0) * U_ + u], a0);
        a1 = fmaf(row[k + 1], A[(k + 1) * U_ + u], a1);
        a2 = fmaf(row[k + 2], A[(k + 2) * U_ + u], a2);
        a3 = fmaf(row[k + 3], A[(k + 3) * U_ + u], a3);
    }
    g_M[r * U_ + u] = (a0 + a1) + (a2 + a3);
    g_M[(64 + r) * U_ + u] = row[u];
}

// ---------------------------------------------------------------------------
// K-C: buildSmall.  bid<64: KC row = KT[r]@CyT ; bid>=64: ACyT row = A[r]@CyT
// ---------------------------------------------------------------------------
__global__ __launch_bounds__(64) void buildSmall(const float* __restrict__ KT,
                                                 const float* __restrict__ A,
                                                 const float* __restrict__ CyT) {
    const int bid = blockIdx.x, o = threadIdx.x;
    __shared__ float row[U_];
    const float* src = (bid < 64) ? (KT + (size_t)bid * U_)
                                  : (A + (size_t)(bid - 64) * U_);
    row[o] = src[o];
    row[o + 64] = src[o + 64];
    __syncthreads();
    float a0 = 0.f, a1 = 0.f, a2 = 0.f, a3 = 0.f;
#pragma unroll
    for (int k = 0; k < U_; k += 4) {
        a0 = fmaf(row[k + 0], CyT[(k + 0) * NOUT + o], a0);
        a1 = fmaf(row[k + 1], CyT[(k + 1) * NOUT + o], a1);
        a2 = fmaf(row[k + 2], CyT[(k + 2) * NOUT + o], a2);
        a3 = fmaf(row[k + 3], CyT[(k + 3) * NOUT + o], a3);
    }
    const float v = (a0 + a1) + (a2 + a3);
    if (bid < 64) g_KC[bid * NOUT + o] = v;
    else          g_ACyT[(bid - 64) * NOUT + o] = v;
}

// ---------------------------------------------------------------------------
// K-D: zbuild.  Z = xpair @ M, xpair rows = contiguous 128 floats of x.
// x viewed as [B*HT, 128].  256 rows/CTA, grid 512.
// ---------------------------------------------------------------------------
__global__ __launch_bounds__(128) void zbuild(const float* __restrict__ x) {
    const int u = threadIdx.x;
    float kt[U_];
#pragma unroll
    for (int n = 0; n < U_; n++) kt[n] = g_M[n * U_ + u];

    __shared__ __align__(16) float xs[U_ * 8];   // 4 KB, [n][r]
    const int row0 = blockIdx.x * 256;

#pragma unroll 1
    for (int tile = 0; tile < 32; tile++) {
        const int r0 = row0 + tile * 8;
        // 8 rows x 128 floats = 256 float4 ; 2 per thread
        const float4* xb = (const float4*)x + (size_t)r0 * 32;
        float4 xv0 = xb[u];
        float4 xv1 = xb[u + 128];
        __syncthreads();
        {
            const int rr = u >> 5;           // 0..3
            const int n0 = (u & 31) * 4;
            xs[(n0 + 0) * 8 + rr] = xv0.x;
            xs[(n0 + 1) * 8 + rr] = xv0.y;
            xs[(n0 + 2) * 8 + rr] = xv0.z;
            xs[(n0 + 3) * 8 + rr] = xv0.w;
            xs[(n0 + 0) * 8 + rr + 4] = xv1.x;
            xs[(n0 + 1) * 8 + rr + 4] = xv1.y;
            xs[(n0 + 2) * 8 + rr + 4] = xv1.z;
            xs[(n0 + 3) * 8 + rr + 4] = xv1.w;
        }
        __syncthreads();

        unsigned long long acc[4] = {0ull, 0ull, 0ull, 0ull};
#pragma unroll
        for (int n = 0; n < U_; n++) {
            const unsigned long long kv = dup2(kt[n]);
            ulonglong2 a = *(const ulonglong2*)&xs[n * 8];
            ulonglong2 b = *(const ulonglong2*)&xs[n * 8 + 4];
            acc[0] = ffma2(a.x, kv, acc[0]);
            acc[1] = ffma2(a.y, kv, acc[1]);
            acc[2] = ffma2(b.x, kv, acc[2]);
            acc[3] = ffma2(b.y, kv, acc[3]);
        }
#pragma unroll
        for (int i = 0; i < 4; i++) {
            float2 f = unpack2(acc[i]);
            g_Z[(size_t)(r0 + 2 * i)     * U_ + u] = f.x;
            g_Z[(size_t)(r0 + 2 * i + 1) * U_ + u] = f.y;
        }
    }
}

// ---------------------------------------------------------------------------
// K-E: scan.  e_i = Z_i + e_{i-1}@A2, chunk-local zero init, 32 steps.
// 16 batches/CTA, grid (64 chunks, 4) = 256 CTAs = one wave at occ 2.
// A2 column in registers (occ 2 => 255-reg budget, no spill).
// ---------------------------------------------------------------------------
__global__ __launch_bounds__(128, 2) void scan_kernel() {
    const int c = blockIdx.x, bg = blockIdx.y, u = threadIdx.x;
    const int b0 = bg * 16;

    __shared__ __align__(16) float s_sh[2][U_ * 16];   // 16 KB

    float at2[U_];
#pragma unroll
    for (int k = 0; k < U_; k++) at2[k] = g_A2[k * U_ + u];

#pragma unroll
    for (int j = 0; j < 16; j++) s_sh[0][u * 16 + j] = 0.f;
    __syncthreads();

    const int i0 = c * HCH;
    float zc[16];
#pragma unroll
    for (int j = 0; j < 16; j++)
        zc[j] = g_Z[((size_t)(b0 + j) * HT + i0) * U_ + u];

    int p = 0;
#pragma unroll 1
    for (int it = 0; it < HCH; it++) {
        const int i = i0 + it;

        float zn[16];
        if (it < HCH - 1) {
#pragma unroll
            for (int j = 0; j < 16; j++)
                zn[j] = g_Z[((size_t)(b0 + j) * HT + i + 1) * U_ + u];
        } else {
#pragma unroll
            for (int j = 0; j < 16; j++) zn[j] = 0.f;
        }

        unsigned long long acc[8];
#pragma unroll
        for (int q = 0; q < 8; q++) acc[q] = pack2(zc[2 * q], zc[2 * q + 1]);

#pragma unroll
        for (int k = 0; k < U_; k++) {
            const unsigned long long av = dup2(at2[k]);
            const ulonglong2 s0 = *(const ulonglong2*)&s_sh[p][k * 16 + 0];
            const ulonglong2 s1 = *(const ulonglong2*)&s_sh[p][k * 16 + 4];
            const ulonglong2 s2 = *(const ulonglong2*)&s_sh[p][k * 16 + 8];
            const ulonglong2 s3 = *(const ulonglong2*)&s_sh[p][k * 16 + 12];
            acc[0] = ffma2(s0.x, av, acc[0]);
            acc[1] = ffma2(s0.y, av, acc[1]);
            acc[2] = ffma2(s1.x, av, acc[2]);
            acc[3] = ffma2(s1.y, av, acc[3]);
            acc[4] = ffma2(s2.x, av, acc[4]);
            acc[5] = ffma2(s2.y, av, acc[5]);
            acc[6] = ffma2(s3.x, av, acc[6]);
            acc[7] = ffma2(s3.y, av, acc[7]);
        }

        const int q = p ^ 1;
        float2 f0 = unpack2(acc[0]), f1 = unpack2(acc[1]);
        float2 f2 = unpack2(acc[2]), f3 = unpack2(acc[3]);
        float2 f4 = unpack2(acc[4]), f5 = unpack2(acc[5]);
        float2 f6 = unpack2(acc[6]), f7 = unpack2(acc[7]);
        {
            float4* dst = (float4*)&s_sh[q][u * 16];
            dst[0] = make_float4(f0.x, f0.y, f1.x, f1.y);
            dst[1] = make_float4(f2.x, f2.y, f3.x, f3.y);
            dst[2] = make_float4(f4.x, f4.y, f5.x, f5.y);
            dst[3] = make_float4(f6.x, f6.y, f7.x, f7.y);
        }
        // coalesced store of odd states
        g_S[((size_t)(b0 + 0)  * HT + i) * U_ + u] = f0.x;
        g_S[((size_t)(b0 + 1)  * HT + i) * U_ + u] = f0.y;
        g_S[((size_t)(b0 + 2)  * HT + i) * U_ + u] = f1.x;
        g_S[((size_t)(b0 + 3)  * HT + i) * U_ + u] = f1.y;
        g_S[((size_t)(b0 + 4)  * HT + i) * U_ + u] = f2.x;
        g_S[((size_t)(b0 + 5)  * HT + i) * U_ + u] = f2.y;
        g_S[((size_t)(b0 + 6)  * HT + i) * U_ + u] = f3.x;
        g_S[((size_t)(b0 + 7)  * HT + i) * U_ + u] = f3.y;
        g_S[((size_t)(b0 + 8)  * HT + i) * U_ + u] = f4.x;
        g_S[((size_t)(b0 + 9)  * HT + i) * U_ + u] = f4.y;
        g_S[((size_t)(b0 + 10) * HT + i) * U_ + u] = f5.x;
        g_S[((size_t)(b0 + 11) * HT + i) * U_ + u] = f5.y;
        g_S[((size_t)(b0 + 12) * HT + i) * U_ + u] = f6.x;
        g_S[((size_t)(b0 + 13) * HT + i) * U_ + u] = f6.y;
        g_S[((size_t)(b0 + 14) * HT + i) * U_ + u] = f7.x;
        g_S[((size_t)(b0 + 15) * HT + i) * U_ + u] = f7.y;
        __syncthreads();

        p = q;
#pragma unroll
        for (int j = 0; j < 16; j++) zc[j] = zn[j];
    }
}

// ---------------------------------------------------------------------------
// K-F: carry scan.  carry[b,0]=0; carry[b,c] = E[b,c-1] + carry[b,c-1]@A64
// E[b,c] = g_S[b][c*32+31]  (chunk-end local state, t'=63 is odd)
// ---------------------------------------------------------------------------
__global__ __launch_bounds__(128) void pass2_kernel() {
    const int b = blockIdx.x, u = threadIdx.x;
    __shared__ float ss[2][U_];
    float m[U_];
#pragma unroll
    for (int k = 0; k < U_; k++) m[k] = g_A64[k * U_ + u];

    float su = 0.f;
    float e = g_S[((size_t)b * HT + (HCH - 1)) * U_ + u];
    ss[0][u] = 0.f;
    __syncthreads();

    int p = 0;
#pragma unroll 1
    for (int c = 0; c < CCH; c++) {
        g_carry[((size_t)b * CCH + c) * U_ + u] = su;
        float a0 = e, a1 = 0.f, a2 = 0.f, a3 = 0.f;
        if (c < CCH - 1)
            e = g_S[((size_t)b * HT + (c + 1) * HCH + (HCH - 1)) * U_ + u];
#pragma unroll
        for (int k = 0; k < U_; k += 4) {
            a0 = fmaf(ss[p][k + 0], m[k + 0], a0);
            a1 = fmaf(ss[p][k + 1], m[k + 1], a1);
            a2 = fmaf(ss[p][k + 2], m[k + 2], a2);
            a3 = fmaf(ss[p][k + 3], m[k + 3], a3);
        }
        su = (a0 + a1) + (a2 + a3);
        ss[p ^ 1][u] = su;
        __syncthreads();
        p ^= 1;
    }
}

// ---------------------------------------------------------------------------
// K-G: wbuild. CTA s: W[s] = A^(s+1)@CyT via binary power chain. 64KB dyn smem.
// ---------------------------------------------------------------------------
__global__ __launch_bounds__(512) void wbuild(const float* __restrict__ A1,
                                              const float* __restrict__ CyT) {
    extern __shared__ float V[];
    float* cur = V;
    float* nxt = V + 8192;
    const int s = blockIdx.x;
    const int n = s + 1;
    const int tid = threadIdx.x;
    const int o = tid & 63, kg = tid >> 6;

    for (int i = tid; i < U_ * NOUT; i += 512) cur[i] = CyT[i];
    __syncthreads();

#pragma unroll 1
    for (int b = 0; b < 7; b++) {
        if (!((n >> b) & 1)) continue;
        const float* P = (b == 0) ? A1
                       : (b == 1) ? g_A2  : (b == 2) ? g_A4
                       : (b == 3) ? g_A8  : (b == 4) ? g_A16
                       : (b == 5) ? g_A32 : g_A64;
#pragma unroll 1
        for (int i = 0; i < 16; i++) {
            const int k = kg * 16 + i;
            float a0 = 0.f, a1 = 0.f, a2 = 0.f, a3 = 0.f;
#pragma unroll
            for (int m = 0; m < U_; m += 4) {
                a0 = fmaf(P[k * U_ + m + 0], cur[(m + 0) * 64 + o], a0);
                a1 = fmaf(P[k * U_ + m + 1], cur[(m + 1) * 64 + o], a1);
                a2 = fmaf(P[k * U_ + m + 2], cur[(m + 2) * 64 + o], a2);
                a3 = fmaf(P[k * U_ + m + 3], cur[(m + 3) * 64 + o], a3);
            }
            nxt[k * 64 + o] = (a0 + a1) + (a2 + a3);
        }
        __syncthreads();
        float* tmp = cur; cur = nxt; nxt = tmp;
    }

#pragma unroll 1
    for (int i = 0; i < 16; i++) {
        const int k = kg * 16 + i;
        g_Wt[(size_t)k * (LCH * NOUT) + s * 64 + o] = cur[k * 64 + o];
    }
}

// ---------------------------------------------------------------------------
// K-H: fixup  y = carry @ Wt  (WRITES all of y).  M=4096 (b,c), N=4096, K=128.
// ---------------------------------------------------------------------------
__global__ __launch_bounds__(128, 2) void fixup(float* __restrict__ y) {
    const int nt = blockIdx.x, mt = blockIdx.y;
    const int tid = threadIdx.x;
    __shared__ __align__(16) float As[U_ * 64];
    __shared__ __align__(16) float Bs[U_ * 32];

    {
        const int mi = tid >> 1, kh = (tid & 1) * 64;
        const float* src = &g_carry[((size_t)(mt * 64 + mi)) * U_ + kh];
#pragma unroll
        for (int i = 0; i < 64; i += 4) {
            float4 v = *(const float4*)(src + i);
            As[(kh + i + 0) * 64 + mi] = v.x;
            As[(kh + i + 1) * 64 + mi] = v.y;
            As[(kh + i + 2) * 64 + mi] = v.z;
            As[(kh + i + 3) * 64 + mi] = v.w;
        }
    }
    {
        const float4* src = (const float4*)&g_Wt[(size_t)tid * (LCH * NOUT) + nt * 32];
        float4* dst = (float4*)&Bs[tid * 32];
#pragma unroll
        for (int i = 0; i < 8; i++) dst[i] = src[i];
    }
    __syncthreads();

    const int ni = tid & 7, mi = tid >> 3;
    const int n4 = ni * 4, m4 = mi * 4;

    unsigned long long acc[4][2];
#pragma unroll
    for (int i = 0; i < 4; i++) { acc[i][0] = 0ull; acc[i][1] = 0ull; }

#pragma unroll 8
    for (int k = 0; k < U_; k++) {
        const float4 a = *(const float4*)&As[k * 64 + m4];
        const ulonglong2 b = *(const ulonglong2*)&Bs[k * 32 + n4];
        const unsigned long long a0 = dup2(a.x), a1 = dup2(a.y);
        const unsigned long long a2 = dup2(a.z), a3 = dup2(a.w);
        acc[0][0] = ffma2(b.x, a0, acc[0][0]);
        acc[0][1] = ffma2(b.y, a0, acc[0][1]);
        acc[1][0] = ffma2(b.x, a1, acc[1][0]);
        acc[1][1] = ffma2(b.y, a1, acc[1][1]);
        acc[2][0] = ffma2(b.x, a2, acc[2][0]);
        acc[2][1] = ffma2(b.y, a2, acc[2][1]);
        acc[3][0] = ffma2(b.x, a3, acc[3][0]);
        acc[3][1] = ffma2(b.y, a3, acc[3][1]);
    }

#pragma unroll
    for (int i = 0; i < 4; i++) {
        const int r = mt * 64 + m4 + i;
        float* yp = y + (size_t)r * 4096 + nt * 32 + n4;
        float2 f0 = unpack2(acc[i][0]), f1 = unpack2(acc[i][1]);
        *(float4*)yp = make_float4(f0.x, f0.y, f1.x, f1.y);
    }
}

// ---------------------------------------------------------------------------
// K-I: y_odd.  y[b,2i+1,:] += e_i @ CyT.  rows = B*HT, 64/CTA, 64KB dyn smem.
// ---------------------------------------------------------------------------
__global__ __launch_bounds__(128) void y_odd(const float* __restrict__ CyT,
                                             float* __restrict__ y) {
    extern __shared__ float sm[];
    float* As = sm;           // [128][64]
    float* Bs = sm + 8192;    // [128][64]
    const int tid = threadIdx.x;
    const int row0 = blockIdx.x * 64;

    {
        const int mi = tid >> 1, kh = (tid & 1) * 64;
        const float* src = g_S + (size_t)(row0 + mi) * U_ + kh;
#pragma unroll
        for (int j = 0; j < 64; j += 4) {
            float4 v = *(const float4*)(src + j);
            As[(kh + j + 0) * 64 + mi] = v.x;
            As[(kh + j + 1) * 64 + mi] = v.y;
            As[(kh + j + 2) * 64 + mi] = v.z;
            As[(kh + j + 3) * 64 + mi] = v.w;
        }
    }
    {
        const float4* src = (const float4*)CyT + (size_t)tid * 16;
        float4* dst = (float4*)(Bs + tid * 64);
#pragma unroll
        for (int j = 0; j < 16; j++) dst[j] = src[j];
    }
    __syncthreads();

    const int ni = tid & 15, mg = tid >> 4;
    const int n4 = ni * 4, m0 = mg * 8;
    unsigned long long acc[4][4] = {};
#pragma unroll 16
    for (int k = 0; k < U_; k++) mma8x4<64>(acc, As, Bs, k, m0, n4);

#pragma unroll
    for (int p = 0; p < 4; p++) {
        float2 q0 = unpack2(acc[p][0]), q1 = unpack2(acc[p][1]);
        float2 q2 = unpack2(acc[p][2]), q3 = unpack2(acc[p][3]);
        const int r = row0 + m0 + 2 * p;
        {
            const int b = r >> 11, i = r & (HT - 1);
            float* yp = y + ((size_t)b * T_ + 2 * i + 1) * NOUT + n4;
            float4 e = *(float4*)yp;
            *(float4*)yp = make_float4(e.x + q0.x, e.y + q1.x, e.z + q2.x, e.w + q3.x);
        }
        {
            const int r1 = r + 1;
            const int b = r1 >> 11, i = r1 & (HT - 1);
            float* yp = y + ((size_t)b * T_ + 2 * i + 1) * NOUT + n4;
            float4 e = *(float4*)yp;
            *(float4*)yp = make_float4(e.x + q0.y, e.y + q1.y, e.z + q2.y, e.w + q3.y);
        }
    }
}

// ---------------------------------------------------------------------------
// K-J: y_even.  y[b,2i,:] += x[2i]@KC + e_{i-1}@ACyT  (e_{-1 of chunk} = 0).
// Two-phase accumulate, 64KB dyn smem.
// ---------------------------------------------------------------------------
__global__ __launch_bounds__(128) void y_even(const float* __restrict__ x,
                                              float* __restrict__ y) {
    extern __shared__ float sm[];
    float* As = sm;           // up to [128][64]
    float* Bs = sm + 8192;    // up to [128][64]
    const int tid = threadIdx.x;
    const int row0 = blockIdx.x * 64;
    const int ni = tid & 15, mg = tid >> 4;
    const int n4 = ni * 4, m0 = mg * 8;

    unsigned long long acc[4][4] = {};

    // ---- phase 1: x_even @ KC  (K = 64) ----
    {
        const int mi = tid >> 1, kh = (tid & 1) * 32;
        const int r = row0 + mi;
        const int b = r >> 11, i = r & (HT - 1);
        const float* src = x + ((size_t)b * T_ + 2 * i) * NIN + kh;
#pragma unroll
        for (int j = 0; j < 32; j += 4) {
            float4 v = *(const float4*)(src + j);
            As[(kh + j + 0) * 64 + mi] = v.x;
            As[(kh + j + 1) * 64 + mi] = v.y;
            As[(kh + j + 2) * 64 + mi] = v.z;
            As[(kh + j + 3) * 64 + mi] = v.w;
        }
        const float4* csrc = (const float4*)g_KC;
        float4* cdst = (float4*)Bs;
#pragma unroll
        for (int j = 0; j < 8; j++) cdst[tid + j * 128] = csrc[tid + j * 128];
    }
    __syncthreads();
#pragma unroll 16
    for (int k = 0; k < NIN; k++) mma8x4<64>(acc, As, Bs, k, m0, n4);
    __syncthreads();

    // ---- phase 2: e_{i-1} @ ACyT  (K = 128) ----
    {
        const int mi = tid >> 1, kh = (tid & 1) * 64;
        const int r = row0 + mi;
        const int b = r >> 11, i = r & (HT - 1);
        if ((i & (HCH - 1)) == 0) {
#pragma unroll
            for (int j = 0; j < 64; j++) As[(kh + j) * 64 + mi] = 0.f;
        } else {
            const float* src = g_S + ((size_t)b * HT + i - 1) * U_ + kh;
#pragma unroll
            for (int j = 0; j < 64; j += 4) {
                float4 v = *(const float4*)(src + j);
                As[(kh + j + 0) * 64 + mi] = v.x;
                As[(kh + j + 1) * 64 + mi] = v.y;
                As[(kh + j + 2) * 64 + mi] = v.z;
                As[(kh + j + 3) * 64 + mi] = v.w;
            }
        }
        const float4* wsrc = (const float4*)g_ACyT;
        float4* wdst = (float4*)Bs;
#pragma unroll
        for (int j = 0; j < 16; j++) wdst[tid + j * 128] = wsrc[tid + j * 128];
    }
    __syncthreads();
#pragma unroll 16
    for (int k = 0; k < U_; k++) mma8x4<64>(acc, As, Bs, k, m0, n4);

#pragma unroll
    for (int p = 0; p < 4; p++) {
        float2 q0 = unpack2(acc[p][0]), q1 = unpack2(acc[p][1]);
        float2 q2 = unpack2(acc[p][2]), q3 = unpack2(acc[p][3]);
#pragma unroll
        for (int h = 0; h < 2; h++) {
            const int r = row0 + m0 + 2 * p + h;
            const int b = r >> 11, i = r & (HT - 1);
            float* yp = y + ((size_t)b * T_ + 2 * i) * NOUT + n4;
            float4 e = *(float4*)yp;
            float4 q = (h == 0) ? make_float4(q0.x, q1.x, q2.x, q3.x)
                                : make_float4(q0.y, q1.y, q2.y, q3.y);
            *(float4*)yp = make_float4(e.x + q.x, e.y + q.y, e.z + q.z, e.w + q.w);
        }
    }
}

// ---------------------------------------------------------------------------
// Launch.  #3 = zbuild, #4 = scan (ncu candidates).
// ---------------------------------------------------------------------------
extern "C" void kernel_launch(void* const* d_in, const int* in_sizes, int n_in,
                              void* d_out, int out_size) {
    const float* x   = (const float*)d_in[0];
    const float* AT  = (const float*)d_in[1];
    const float* KT  = (const float*)d_in[2];
    const float* CyT = (const float*)d_in[3];
    float* y = (float*)d_out;

    float *A2, *A4, *A8, *A16, *A32, *A64;
    cudaGetSymbolAddress((void**)&A2,  g_A2);
    cudaGetSymbolAddress((void**)&A4,  g_A4);
    cudaGetSymbolAddress((void**)&A8,  g_A8);
    cudaGetSymbolAddress((void**)&A16, g_A16);
    cudaGetSymbolAddress((void**)&A32, g_A32);
    cudaGetSymbolAddress((void**)&A64, g_A64);

    cudaFuncSetAttribute(wbuild, cudaFuncAttributeMaxDynamicSharedMemorySize, 65536);
    cudaFuncSetAttribute(y_odd,  cudaFuncAttributeMaxDynamicSharedMemorySize, 65536);
    cudaFuncSetAttribute(y_even, cudaFuncAttributeMaxDynamicSharedMemorySize, 65536);

    matsq<<<128, 128>>>(AT, A2);                         // 1
    buildM<<<64, 128>>>(KT, AT);                         // 2
    zbuild<<<(B_ * HT) / 256, 128>>>(x);                 // 3  <- ncu candidate
    scan_kernel<<<dim3(CCH, 4), 128>>>();                // 4  <- ncu candidate
    matsq<<<128, 128>>>(A2,  A4);                        // 5
    matsq<<<128, 128>>>(A4,  A8);                        // 6
    matsq<<<128, 128>>>(A8,  A16);                       // 7
    matsq<<<128, 128>>>(A16, A32);                       // 8
    matsq<<<128, 128>>>(A32, A64);                       // 9
    buildSmall<<<192, 64>>>(KT, AT, CyT);                // 10
    pass2_kernel<<<B_, 128>>>();                         // 11
    wbuild<<<LCH, 512, 65536>>>(AT, CyT);                // 12
    fixup<<<dim3(128, 64), 128>>>(y);                    // 13 (writes y)
    y_odd<<<(B_ * HT) / 64, 128, 65536>>>(CyT, y);       // 14 (+= odd t)
    y_even<<<(B_ * HT) / 64, 128, 65536>>>(x, y);        // 15 (+= even t)
}

// round 7
// speedup vs baseline: 2.3064x; 1.3458x over previous
#include <cuda_runtime.h>
#include <cstdint>

#define B_   64
#define T_   4096
#define NIN  64
#define U_   128
#define NOUT 64
#define CCH  64     // chunks (per batch)
#define LCH  64     // timesteps per chunk
#define HT   2048   // T/2 : odd-state (pair) count per batch
#define HCH  32     // odd states per chunk

#define ASTRIDE 129          // padded A row stride in smem (floats)
#define AS_FLOATS (128 * ASTRIDE)

// ---------------------------------------------------------------------------
// Static device scratch
// ---------------------------------------------------------------------------
__device__ float g_Z[B_ * HT * U_];       // 64 MB : Z_i = ky[2i+1] + ky[2i]@A
__device__ float g_S[B_ * HT * U_];       // 64 MB : chunk-local odd states e_i
__device__ float g_carry[B_ * CCH * U_];
__device__ float g_M[U_ * U_];            // stacked [[KT@A],[KT]]
__device__ float g_KC[NIN * NOUT];        // KT@CyT   [64,64]
__device__ float g_ACyT[U_ * NOUT];       // A@CyT    [128,64]
__device__ float g_A2[U_ * U_], g_A4[U_ * U_], g_A8[U_ * U_];
__device__ float g_A16[U_ * U_], g_A32[U_ * U_], g_A64[U_ * U_];
__device__ float g_Wt[U_ * LCH * NOUT];   // [k][step*64+o]; W[s] = A^(s+1)@CyT

// ---------------------------------------------------------------------------
// Packed f32x2 helpers
// ---------------------------------------------------------------------------
__device__ __forceinline__ unsigned long long ffma2(unsigned long long a,
                                                    unsigned long long b,
                                                    unsigned long long c) {
    unsigned long long d;
    asm("fma.rn.f32x2 %0, %1, %2, %3;" : "=l"(d) : "l"(a), "l"(b), "l"(c));
    return d;
}
__device__ __forceinline__ unsigned long long dup2(float v) {
    unsigned long long r;
    asm("mov.b64 %0, {%1, %1};" : "=l"(r) : "f"(v));
    return r;
}
__device__ __forceinline__ unsigned long long pack2(float x, float y) {
    unsigned long long r;
    asm("mov.b64 %0, {%1, %2};" : "=l"(r) : "f"(x), "f"(y));
    return r;
}
__device__ __forceinline__ float2 unpack2(unsigned long long v) {
    float2 f;
    asm("mov.b64 {%0, %1}, %2;" : "=f"(f.x), "=f"(f.y) : "l"(v));
    return f;
}

// ---------------------------------------------------------------------------
// 8m x 8n register tile step.  As row-major [m][ASTRIDE], Bs [k][64].
// acc[i][j] = f32x2 over n-pair (n0+2j, n0+2j+1) for row m0+i.
// ---------------------------------------------------------------------------
__device__ __forceinline__ void mma8x8(unsigned long long acc[8][4],
                                       const float* __restrict__ As,
                                       const float* __restrict__ Bs,
                                       int k, int m0, int n0) {
    float a[8];
#pragma unroll
    for (int i = 0; i < 8; i++) a[i] = As[(m0 + i) * ASTRIDE + k];
    const ulonglong2 b0 = *(const ulonglong2*)&Bs[k * 64 + n0];
    const ulonglong2 b1 = *(const ulonglong2*)&Bs[k * 64 + n0 + 4];
#pragma unroll
    for (int i = 0; i < 8; i++) {
        const unsigned long long ai = dup2(a[i]);
        acc[i][0] = ffma2(b0.x, ai, acc[i][0]);
        acc[i][1] = ffma2(b0.y, ai, acc[i][1]);
        acc[i][2] = ffma2(b1.x, ai, acc[i][2]);
        acc[i][3] = ffma2(b1.y, ai, acc[i][3]);
    }
}

// Stage a contiguous [128 rows][128] A tile row-major into padded smem.
// 128 threads, coalesced LDG.128, conflict-free scalar STS.
__device__ __forceinline__ void stageA128(float* As, const float* __restrict__ gsrc,
                                          int t) {
#pragma unroll
    for (int j = 0; j < 32; j++) {
        const int f = j * 128 + t;                 // float4 id
        const float4 v = *(const float4*)(gsrc + 4 * f);
        const int row = f >> 5;
        const int kk = (f & 31) * 4;
        float* d = As + row * ASTRIDE + kk;
        d[0] = v.x; d[1] = v.y; d[2] = v.z; d[3] = v.w;
    }
}

// Stage Bs[k][0..63] <- gsrc[k*stride + 0..63], k = 0..krows-1.
__device__ __forceinline__ void stageB64(float* Bs, const float* __restrict__ gsrc,
                                         int stride, int krows, int t) {
    const int nIt = krows / 8;                     // (krows*16)/128
#pragma unroll
    for (int it = 0; it < 16; it++) {
        if (it >= nIt) break;
        const int f = it * 128 + t;
        const int k = f >> 4, c = (f & 15) * 4;
        *(float4*)&Bs[k * 64 + c] = *(const float4*)(gsrc + (size_t)k * stride + c);
    }
}

// ---------------------------------------------------------------------------
// K-A: matsq  O = A @ A
// ---------------------------------------------------------------------------
__global__ __launch_bounds__(128) void matsq(const float* __restrict__ A,
                                             float* __restrict__ O) {
    const int r = blockIdx.x, u = threadIdx.x;
    __shared__ float row[U_];
    row[u] = A[r * U_ + u];
    __syncthreads();
    float a0 = 0.f, a1 = 0.f, a2 = 0.f, a3 = 0.f;
#pragma unroll
    for (int k = 0; k < U_; k += 4) {
        a0 = fmaf(row[k + 0], A[(k + 0) * U_ + u], a0);
        a1 = fmaf(row[k + 1], A[(k + 1) * U_ + u], a1);
        a2 = fmaf(row[k + 2], A[(k + 2) * U_ + u], a2);
        a3 = fmaf(row[k + 3], A[(k + 3) * U_ + u], a3);
    }
    O[r * U_ + u] = (a0 + a1) + (a2 + a3);
}

// ---------------------------------------------------------------------------
// K-B: buildM.  M[0:64] = KT@A (row r), M[64:128] = KT (copy).
// ---------------------------------------------------------------------------
__global__ __launch_bounds__(128) void buildM(const float* __restrict__ KT,
                                              const float* __restrict__ A) {
    const int r = blockIdx.x, u = threadIdx.x;
    __shared__ float row[U_];
    row[u] = KT[r * U_ + u];
    __syncthreads();
    float a0 = 0.f, a1 = 0.f, a2 = 0.f, a3 = 0.f;
#pragma unroll
    for (int k = 0; k < U_; k += 4) {
        a0 = fmaf(row[k + 0], A[(k + 0) * U_ + u], a0);
        a1 = fmaf(row[k + 1], A[(k + 1) * U_ + u], a1);
        a2 = fmaf(row[k + 2], A[(k + 2) * U_ + u], a2);
        a3 = fmaf(row[k + 3], A[(k + 3) * U_ + u], a3);
    }
    g_M[r * U_ + u] = (a0 + a1) + (a2 + a3);
    g_M[(64 + r) * U_ + u] = row[u];
}

// ---------------------------------------------------------------------------
// K-C: buildSmall.  bid<64: KC row = KT[r]@CyT ; bid>=64: ACyT row = A[r]@CyT
// ---------------------------------------------------------------------------
__global__ __launch_bounds__(64) void buildSmall(const float* __restrict__ KT,
                                                 const float* __restrict__ A,
                                                 const float* __restrict__ CyT) {
    const int bid = blockIdx.x, o = threadIdx.x;
    __shared__ float row[U_];
    const float* src = (bid < 64) ? (KT + (size_t)bid * U_)
                                  : (A + (size_t)(bid - 64) * U_);
    row[o] = src[o];
    row[o + 64] = src[o + 64];
    __syncthreads();
    float a0 = 0.f, a1 = 0.f, a2 = 0.f, a3 = 0.f;
#pragma unroll
    for (int k = 0; k < U_; k += 4) {
        a0 = fmaf(row[k + 0], CyT[(k + 0) * NOUT + o], a0);
        a1 = fmaf(row[k + 1], CyT[(k + 1) * NOUT + o], a1);
        a2 = fmaf(row[k + 2], CyT[(k + 2) * NOUT + o], a2);
        a3 = fmaf(row[k + 3], CyT[(k + 3) * NOUT + o], a3);
    }
    const float v = (a0 + a1) + (a2 + a3);
    if (bid < 64) g_KC[bid * NOUT + o] = v;
    else          g_ACyT[(bid - 64) * NOUT + o] = v;
}

// ---------------------------------------------------------------------------
// K-D: zbuild8x8.  Z = xpair @ M.  M-rows 131072 (128/CTA), N=128 (64/ntile).
// grid (1024, 2), 128 threads, 98.8KB dyn smem (2 CTAs/SM).
// ---------------------------------------------------------------------------
__global__ __launch_bounds__(128) void zbuild8(const float* __restrict__ x) {
    extern __shared__ __align__(16) float sm[];
    float* As = sm;
    float* Bs = sm + AS_FLOATS;
    const int t = threadIdx.x;
    const int row0 = blockIdx.x * 128;
    const int nt = blockIdx.y;

    stageA128(As, x + (size_t)row0 * 128, t);
    stageB64(Bs, g_M + nt * 64, 128, 128, t);
    __syncthreads();

    const int mg = t >> 3, ng = t & 7;
    const int m0 = mg * 8, n0 = ng * 8;
    unsigned long long acc[8][4] = {};
#pragma unroll 4
    for (int k = 0; k < 128; k++) mma8x8(acc, As, Bs, k, m0, n0);

#pragma unroll
    for (int i = 0; i < 8; i++) {
        float2 p0 = unpack2(acc[i][0]), p1 = unpack2(acc[i][1]);
        float2 p2 = unpack2(acc[i][2]), p3 = unpack2(acc[i][3]);
        float* zp = g_Z + (size_t)(row0 + m0 + i) * U_ + nt * 64 + n0;
        *(float4*)(zp)     = make_float4(p0.x, p0.y, p1.x, p1.y);
        *(float4*)(zp + 4) = make_float4(p2.x, p2.y, p3.x, p3.y);
    }
}

// ---------------------------------------------------------------------------
// K-E: scan (verified R6).  e_i = Z_i + e_{i-1}@A2, 32 steps, 16 batches/CTA.
// ---------------------------------------------------------------------------
__global__ __launch_bounds__(128, 2) void scan_kernel() {
    const int c = blockIdx.x, bg = blockIdx.y, u = threadIdx.x;
    const int b0 = bg * 16;

    __shared__ __align__(16) float s_sh[2][U_ * 16];

    float at2[U_];
#pragma unroll
    for (int k = 0; k < U_; k++) at2[k] = g_A2[k * U_ + u];

#pragma unroll
    for (int j = 0; j < 16; j++) s_sh[0][u * 16 + j] = 0.f;
    __syncthreads();

    const int i0 = c * HCH;
    float zc[16];
#pragma unroll
    for (int j = 0; j < 16; j++)
        zc[j] = g_Z[((size_t)(b0 + j) * HT + i0) * U_ + u];

    int p = 0;
#pragma unroll 1
    for (int it = 0; it < HCH; it++) {
        const int i = i0 + it;

        float zn[16];
        if (it < HCH - 1) {
#pragma unroll
            for (int j = 0; j < 16; j++)
                zn[j] = g_Z[((size_t)(b0 + j) * HT + i + 1) * U_ + u];
        } else {
#pragma unroll
            for (int j = 0; j < 16; j++) zn[j] = 0.f;
        }

        unsigned long long acc[8];
#pragma unroll
        for (int q = 0; q < 8; q++) acc[q] = pack2(zc[2 * q], zc[2 * q + 1]);

#pragma unroll
        for (int k = 0; k < U_; k++) {
            const unsigned long long av = dup2(at2[k]);
            const ulonglong2 s0 = *(const ulonglong2*)&s_sh[p][k * 16 + 0];
            const ulonglong2 s1 = *(const ulonglong2*)&s_sh[p][k * 16 + 4];
            const ulonglong2 s2 = *(const ulonglong2*)&s_sh[p][k * 16 + 8];
            const ulonglong2 s3 = *(const ulonglong2*)&s_sh[p][k * 16 + 12];
            acc[0] = ffma2(s0.x, av, acc[0]);
            acc[1] = ffma2(s0.y, av, acc[1]);
            acc[2] = ffma2(s1.x, av, acc[2]);
            acc[3] = ffma2(s1.y, av, acc[3]);
            acc[4] = ffma2(s2.x, av, acc[4]);
            acc[5] = ffma2(s2.y, av, acc[5]);
            acc[6] = ffma2(s3.x, av, acc[6]);
            acc[7] = ffma2(s3.y, av, acc[7]);
        }

        const int q = p ^ 1;
        float2 f0 = unpack2(acc[0]), f1 = unpack2(acc[1]);
        float2 f2 = unpack2(acc[2]), f3 = unpack2(acc[3]);
        float2 f4 = unpack2(acc[4]), f5 = unpack2(acc[5]);
        float2 f6 = unpack2(acc[6]), f7 = unpack2(acc[7]);
        {
            float4* dst = (float4*)&s_sh[q][u * 16];
            dst[0] = make_float4(f0.x, f0.y, f1.x, f1.y);
            dst[1] = make_float4(f2.x, f2.y, f3.x, f3.y);
            dst[2] = make_float4(f4.x, f4.y, f5.x, f5.y);
            dst[3] = make_float4(f6.x, f6.y, f7.x, f7.y);
        }
        g_S[((size_t)(b0 + 0)  * HT + i) * U_ + u] = f0.x;
        g_S[((size_t)(b0 + 1)  * HT + i) * U_ + u] = f0.y;
        g_S[((size_t)(b0 + 2)  * HT + i) * U_ + u] = f1.x;
        g_S[((size_t)(b0 + 3)  * HT + i) * U_ + u] = f1.y;
        g_S[((size_t)(b0 + 4)  * HT + i) * U_ + u] = f2.x;
        g_S[((size_t)(b0 + 5)  * HT + i) * U_ + u] = f2.y;
        g_S[((size_t)(b0 + 6)  * HT + i) * U_ + u] = f3.x;
        g_S[((size_t)(b0 + 7)  * HT + i) * U_ + u] = f3.y;
        g_S[((size_t)(b0 + 8)  * HT + i) * U_ + u] = f4.x;
        g_S[((size_t)(b0 + 9)  * HT + i) * U_ + u] = f4.y;
        g_S[((size_t)(b0 + 10) * HT + i) * U_ + u] = f5.x;
        g_S[((size_t)(b0 + 11) * HT + i) * U_ + u] = f5.y;
        g_S[((size_t)(b0 + 12) * HT + i) * U_ + u] = f6.x;
        g_S[((size_t)(b0 + 13) * HT + i) * U_ + u] = f6.y;
        g_S[((size_t)(b0 + 14) * HT + i) * U_ + u] = f7.x;
        g_S[((size_t)(b0 + 15) * HT + i) * U_ + u] = f7.y;
        __syncthreads();

        p = q;
#pragma unroll
        for (int j = 0; j < 16; j++) zc[j] = zn[j];
    }
}

// ---------------------------------------------------------------------------
// K-F: carry scan (verified R6)
// ---------------------------------------------------------------------------
__global__ __launch_bounds__(128) void pass2_kernel() {
    const int b = blockIdx.x, u = threadIdx.x;
    __shared__ float ss[2][U_];
    float m[U_];
#pragma unroll
    for (int k = 0; k < U_; k++) m[k] = g_A64[k * U_ + u];

    float su = 0.f;
    float e = g_S[((size_t)b * HT + (HCH - 1)) * U_ + u];
    ss[0][u] = 0.f;
    __syncthreads();

    int p = 0;
#pragma unroll 1
    for (int c = 0; c < CCH; c++) {
        g_carry[((size_t)b * CCH + c) * U_ + u] = su;
        float a0 = e, a1 = 0.f, a2 = 0.f, a3 = 0.f;
        if (c < CCH - 1)
            e = g_S[((size_t)b * HT + (c + 1) * HCH + (HCH - 1)) * U_ + u];
#pragma unroll
        for (int k = 0; k < U_; k += 4) {
            a0 = fmaf(ss[p][k + 0], m[k + 0], a0);
            a1 = fmaf(ss[p][k + 1], m[k + 1], a1);
            a2 = fmaf(ss[p][k + 2], m[k + 2], a2);
            a3 = fmaf(ss[p][k + 3], m[k + 3], a3);
        }
        su = (a0 + a1) + (a2 + a3);
        ss[p ^ 1][u] = su;
        __syncthreads();
        p ^= 1;
    }
}

// ---------------------------------------------------------------------------
// K-G: wbuild (verified R6)
// ---------------------------------------------------------------------------
__global__ __launch_bounds__(512) void wbuild(const float* __restrict__ A1,
                                              const float* __restrict__ CyT) {
    extern __shared__ float V[];
    float* cur = V;
    float* nxt = V + 8192;
    const int s = blockIdx.x;
    const int n = s + 1;
    const int tid = threadIdx.x;
    const int o = tid & 63, kg = tid >> 6;

    for (int i = tid; i < U_ * NOUT; i += 512) cur[i] = CyT[i];
    __syncthreads();

#pragma unroll 1
    for (int b = 0; b < 7; b++) {
        if (!((n >> b) & 1)) continue;
        const float* P = (b == 0) ? A1
                       : (b == 1) ? g_A2  : (b == 2) ? g_A4
                       : (b == 3) ? g_A8  : (b == 4) ? g_A16
                       : (b == 5) ? g_A32 : g_A64;
#pragma unroll 1
        for (int i = 0; i < 16; i++) {
            const int k = kg * 16 + i;
            float a0 = 0.f, a1 = 0.f, a2 = 0.f, a3 = 0.f;
#pragma unroll
            for (int m = 0; m < U_; m += 4) {
                a0 = fmaf(P[k * U_ + m + 0], cur[(m + 0) * 64 + o], a0);
                a1 = fmaf(P[k * U_ + m + 1], cur[(m + 1) * 64 + o], a1);
                a2 = fmaf(P[k * U_ + m + 2], cur[(m + 2) * 64 + o], a2);
                a3 = fmaf(P[k * U_ + m + 3], cur[(m + 3) * 64 + o], a3);
            }
            nxt[k * 64 + o] = (a0 + a1) + (a2 + a3);
        }
        __syncthreads();
        float* tmp = cur; cur = nxt; nxt = tmp;
    }

#pragma unroll 1
    for (int i = 0; i < 16; i++) {
        const int k = kg * 16 + i;
        g_Wt[(size_t)k * (LCH * NOUT) + s * 64 + o] = cur[k * 64 + o];
    }
}

// ---------------------------------------------------------------------------
// K-H: fixup8x8.  y = carry @ Wt (WRITES y).  grid (64 nt, 32 mt).
// ---------------------------------------------------------------------------
__global__ __launch_bounds__(128) void fixup8(float* __restrict__ y) {
    extern __shared__ __align__(16) float sm[];
    float* As = sm;
    float* Bs = sm + AS_FLOATS;
    const int t = threadIdx.x;
    const int nt = blockIdx.x, mt = blockIdx.y;
    const int row0 = mt * 128;

    stageA128(As, g_carry + (size_t)row0 * 128, t);
    stageB64(Bs, g_Wt + nt * 64, LCH * NOUT, 128, t);
    __syncthreads();

    const int mg = t >> 3, ng = t & 7;
    const int m0 = mg * 8, n0 = ng * 8;
    unsigned long long acc[8][4] = {};
#pragma unroll 4
    for (int k = 0; k < 128; k++) mma8x8(acc, As, Bs, k, m0, n0);

#pragma unroll
    for (int i = 0; i < 8; i++) {
        float2 p0 = unpack2(acc[i][0]), p1 = unpack2(acc[i][1]);
        float2 p2 = unpack2(acc[i][2]), p3 = unpack2(acc[i][3]);
        float* yp = y + (size_t)(row0 + m0 + i) * 4096 + nt * 64 + n0;
        *(float4*)(yp)     = make_float4(p0.x, p0.y, p1.x, p1.y);
        *(float4*)(yp + 4) = make_float4(p2.x, p2.y, p3.x, p3.y);
    }
}

// ---------------------------------------------------------------------------
// K-I: sgemm8x8.  blockIdx.y==0: y[2i+1] += e_i@CyT.
//                 blockIdx.y==1: y[2i+2] += e_i@ACyT (skip chunk-last i).
// grid (1024, 2).
// ---------------------------------------------------------------------------
__global__ __launch_bounds__(128) void sgemm8(const float* __restrict__ CyT,
                                              float* __restrict__ y) {
    extern __shared__ __align__(16) float sm[];
    float* As = sm;
    float* Bs = sm + AS_FLOATS;
    const int t = threadIdx.x;
    const int row0 = blockIdx.x * 128;
    const int nt = blockIdx.y;

    stageA128(As, g_S + (size_t)row0 * 128, t);
    stageB64(Bs, (nt == 0) ? CyT : g_ACyT, 64, 128, t);
    __syncthreads();

    const int mg = t >> 3, ng = t & 7;
    const int m0 = mg * 8, n0 = ng * 8;
    unsigned long long acc[8][4] = {};
#pragma unroll 4
    for (int k = 0; k < 128; k++) mma8x8(acc, As, Bs, k, m0, n0);

#pragma unroll
    for (int i = 0; i < 8; i++) {
        const int r = row0 + m0 + i;
        const int b = r >> 11, ii = r & (HT - 1);
        if (nt == 1 && (ii & (HCH - 1)) == (HCH - 1)) continue;
        const int trow = (nt == 0) ? (2 * ii + 1) : (2 * ii + 2);
        float2 p0 = unpack2(acc[i][0]), p1 = unpack2(acc[i][1]);
        float2 p2 = unpack2(acc[i][2]), p3 = unpack2(acc[i][3]);
        float* yp = y + ((size_t)b * T_ + trow) * NOUT + n0;
        float4 e0 = *(float4*)(yp);
        float4 e1 = *(float4*)(yp + 4);
        *(float4*)(yp)     = make_float4(e0.x + p0.x, e0.y + p0.y, e0.z + p1.x, e0.w + p1.y);
        *(float4*)(yp + 4) = make_float4(e1.x + p2.x, e1.y + p2.y, e1.z + p3.x, e1.w + p3.y);
    }
}

// ---------------------------------------------------------------------------
// K-J: xkc8x8.  y[2i] += x[2i]@KC.  A = xpair tile (use k<64 only). grid 1024.
// ---------------------------------------------------------------------------
__global__ __launch_bounds__(128) void xkc8(const float* __restrict__ x,
                                            float* __restrict__ y) {
    extern __shared__ __align__(16) float sm[];
    float* As = sm;
    float* Bs = sm + AS_FLOATS;
    const int t = threadIdx.x;
    const int row0 = blockIdx.x * 128;

    stageA128(As, x + (size_t)row0 * 128, t);
    stageB64(Bs, g_KC, 64, 64, t);
    __syncthreads();

    const int mg = t >> 3, ng = t & 7;
    const int m0 = mg * 8, n0 = ng * 8;
    unsigned long long acc[8][4] = {};
#pragma unroll 4
    for (int k = 0; k < 64; k++) mma8x8(acc, As, Bs, k, m0, n0);

#pragma unroll
    for (int i = 0; i < 8; i++) {
        const int r = row0 + m0 + i;
        const int b = r >> 11, ii = r & (HT - 1);
        float2 p0 = unpack2(acc[i][0]), p1 = unpack2(acc[i][1]);
        float2 p2 = unpack2(acc[i][2]), p3 = unpack2(acc[i][3]);
        float* yp = y + ((size_t)b * T_ + 2 * ii) * NOUT + n0;
        float4 e0 = *(float4*)(yp);
        float4 e1 = *(float4*)(yp + 4);
        *(float4*)(yp)     = make_float4(e0.x + p0.x, e0.y + p0.y, e0.z + p1.x, e0.w + p1.y);
        *(float4*)(yp + 4) = make_float4(e1.x + p2.x, e1.y + p2.y, e1.z + p3.x, e1.w + p3.y);
    }
}

// ---------------------------------------------------------------------------
// Launch.  #3 = zbuild8, #4 = scan (ncu candidates).
// ---------------------------------------------------------------------------
extern "C" void kernel_launch(void* const* d_in, const int* in_sizes, int n_in,
                              void* d_out, int out_size) {
    const float* x   = (const float*)d_in[0];
    const float* AT  = (const float*)d_in[1];
    const float* KT  = (const float*)d_in[2];
    const float* CyT = (const float*)d_in[3];
    float* y = (float*)d_out;

    float *A2, *A4, *A8, *A16, *A32, *A64;
    cudaGetSymbolAddress((void**)&A2,  g_A2);
    cudaGetSymbolAddress((void**)&A4,  g_A4);
    cudaGetSymbolAddress((void**)&A8,  g_A8);
    cudaGetSymbolAddress((void**)&A16, g_A16);
    cudaGetSymbolAddress((void**)&A32, g_A32);
    cudaGetSymbolAddress((void**)&A64, g_A64);

    const int SMEM_G = (AS_FLOATS + 128 * 64) * 4;   // 98816 B
    cudaFuncSetAttribute(zbuild8, cudaFuncAttributeMaxDynamicSharedMemorySize, SMEM_G);
    cudaFuncSetAttribute(fixup8,  cudaFuncAttributeMaxDynamicSharedMemorySize, SMEM_G);
    cudaFuncSetAttribute(sgemm8,  cudaFuncAttributeMaxDynamicSharedMemorySize, SMEM_G);
    cudaFuncSetAttribute(xkc8,    cudaFuncAttributeMaxDynamicSharedMemorySize, SMEM_G);
    cudaFuncSetAttribute(wbuild,  cudaFuncAttributeMaxDynamicSharedMemorySize, 65536);

    buildM<<<64, 128>>>(KT, AT);                           // 1
    matsq<<<128, 128>>>(AT, A2);                           // 2
    zbuild8<<<dim3(1024, 2), 128, SMEM_G>>>(x);            // 3  <- ncu candidate
    scan_kernel<<<dim3(CCH, 4), 128>>>();                  // 4  <- ncu candidate
    matsq<<<128, 128>>>(A2,  A4);                          // 5
    matsq<<<128, 128>>>(A4,  A8);                          // 6
    matsq<<<128, 128>>>(A8,  A16);                         // 7
    matsq<<<128, 128>>>(A16, A32);                         // 8
    matsq<<<128, 128>>>(A32, A64);                         // 9
    buildSmall<<<192, 64>>>(KT, AT, CyT);                  // 10
    pass2_kernel<<<B_, 128>>>();                           // 11
    wbuild<<<LCH, 512, 65536>>>(AT, CyT);                  // 12
    fixup8<<<dim3(64, 32), 128, SMEM_G>>>(y);              // 13 (writes y)
    xkc8<<<1024, 128, SMEM_G>>>(x, y);                     // 14 (+= even)
    sgemm8<<<dim3(1024, 2), 128, SMEM_G>>>(CyT, y);        // 15 (+= odd/even)
}

// round 9
// speedup vs baseline: 2.7777x; 1.2043x over previous
#include <cuda_runtime.h>
#include <cuda_bf16.h>
#include <cstdint>

#define B_   64
#define T_   4096
#define NIN  64
#define U_   128
#define NOUT 64
#define CCH  64     // chunks (per batch)
#define LCH  64     // timesteps per chunk
#define HT   2048   // T/2 : pair count per batch
#define HCH  32     // odd states per chunk

#define SSTRIDE 136  // padded bf16 row stride in smem (elements)

// ---------------------------------------------------------------------------
// Static device scratch
// ---------------------------------------------------------------------------
__device__ float g_Z[B_ * HT * U_];       // 64 MB
__device__ float g_S[B_ * HT * U_];       // 64 MB
__device__ float g_carry[B_ * CCH * U_];
__device__ float g_M[U_ * U_];            // stacked [[KT@A],[KT]]  ([k][n])
__device__ float g_KC[NIN * NOUT];        // KT@CyT  [64k][64n]
__device__ float g_ACyT[U_ * NOUT];       // A@CyT   [128k][64n]
__device__ float g_A2[U_ * U_], g_A4[U_ * U_], g_A8[U_ * U_];
__device__ float g_A16[U_ * U_], g_A32[U_ * U_], g_A64[U_ * U_];
__device__ float g_Wt[U_ * LCH * NOUT];   // [k][s*64+o]

// Pre-split bf16 B tiles, layout per tile: [n_local][k] (k contiguous, 128)
__device__ __align__(16) unsigned short g_MT_hi[128 * 128],  g_MT_lo[128 * 128];
__device__ __align__(16) unsigned short g_WT_hi[32 * 128 * 128], g_WT_lo[32 * 128 * 128];
__device__ __align__(16) unsigned short g_CT_hi[64 * 128],   g_CT_lo[64 * 128];
__device__ __align__(16) unsigned short g_ACT_hi[64 * 128],  g_ACT_lo[64 * 128];
__device__ __align__(16) unsigned short g_KCT_hi[64 * 128],  g_KCT_lo[64 * 128];

// ---------------------------------------------------------------------------
// f32x2 helpers (scan path)
// ---------------------------------------------------------------------------
__device__ __forceinline__ unsigned long long ffma2(unsigned long long a,
                                                    unsigned long long b,
                                                    unsigned long long c) {
    unsigned long long d;
    asm("fma.rn.f32x2 %0, %1, %2, %3;" : "=l"(d) : "l"(a), "l"(b), "l"(c));
    return d;
}
__device__ __forceinline__ unsigned long long dup2(float v) {
    unsigned long long r;
    asm("mov.b64 %0, {%1, %1};" : "=l"(r) : "f"(v));
    return r;
}
__device__ __forceinline__ unsigned long long pack2(float x, float y) {
    unsigned long long r;
    asm("mov.b64 %0, {%1, %2};" : "=l"(r) : "f"(x), "f"(y));
    return r;
}
__device__ __forceinline__ float2 unpack2(unsigned long long v) {
    float2 f;
    asm("mov.b64 {%0, %1}, %2;" : "=f"(f.x), "=f"(f.y) : "l"(v));
    return f;
}

// ---------------------------------------------------------------------------
// mma.sync / ldmatrix helpers (base ISA, sm_80+)
// ---------------------------------------------------------------------------
__device__ __forceinline__ uint32_t smem_u32(const void* p) {
    uint32_t a;
    asm("{ .reg .u64 t; cvta.to.shared.u64 t, %1; cvt.u32.u64 %0, t; }"
        : "=r"(a) : "l"(p));
    return a;
}

__device__ __forceinline__ void ldsm4(uint32_t addr, uint32_t r[4]) {
    asm volatile("ldmatrix.sync.aligned.m8n8.x4.shared.b16 {%0,%1,%2,%3}, [%4];"
                 : "=r"(r[0]), "=r"(r[1]), "=r"(r[2]), "=r"(r[3]) : "r"(addr));
}

__device__ __forceinline__ void mma16816(float c[4], const uint32_t a[4],
                                         const uint32_t b[2]) {
    asm volatile(
        "mma.sync.aligned.m16n8k16.row.col.f32.bf16.bf16.f32 "
        "{%0,%1,%2,%3}, {%4,%5,%6,%7}, {%8,%9}, {%0,%1,%2,%3};"
        : "+f"(c[0]), "+f"(c[1]), "+f"(c[2]), "+f"(c[3])
        : "r"(a[0]), "r"(a[1]), "r"(a[2]), "r"(a[3]), "r"(b[0]), "r"(b[1]));
}

__device__ __forceinline__ void split_bf16(float v, unsigned short& h, unsigned short& l) {
    __nv_bfloat16 hb = __float2bfloat16(v);
    float r = v - __bfloat162float(hb);
    __nv_bfloat16 lb = __float2bfloat16(r);
    h = *reinterpret_cast<unsigned short*>(&hb);
    l = *reinterpret_cast<unsigned short*>(&lb);
}

// ---------------------------------------------------------------------------
// prepB: split a fp32 [K][N] matrix (row stride Nsrc) into bf16 hi/lo tiles
// of ntileRows x 128 (k), per-tile layout [n_local][k].  grid = ntiles.
// ---------------------------------------------------------------------------
__global__ __launch_bounds__(256) void prepB(const float* __restrict__ src,
                                             int Ksrc, int Nsrc,
                                             unsigned short* __restrict__ dhi,
                                             unsigned short* __restrict__ dlo,
                                             int ntileRows) {
    const int nt = blockIdx.x;
    const int elems = ntileRows * 128;
    unsigned short* th = dhi + (size_t)nt * elems;
    unsigned short* tl = dlo + (size_t)nt * elems;
    for (int idx = threadIdx.x; idx < elems; idx += 256) {
        const int nl = idx >> 7, k = idx & 127;
        const int n = nt * ntileRows + nl;
        float v = (k < Ksrc) ? src[(size_t)k * Nsrc + n] : 0.f;
        unsigned short h, l;
        split_bf16(v, h, l);
        th[nl * 128 + k] = h;
        tl[nl * 128 + k] = l;
    }
}

// ---------------------------------------------------------------------------
// hgemm: D[128, NTILE] = A[128,128] @ B^T via mma.sync split-bf16.
// MODE 0: out = g_Z rows (write)          grid (1024)         NTILE=128
// MODE 1: out = y, col base by*128 (write) grid (32 mx, 32 by) NTILE=128
// MODE 2: y[b,2i+1] += . (A = g_S)        grid (1024)         NTILE=64
// MODE 3: y[b,2i+2] += . skip chunk-last  grid (1024)         NTILE=64
// MODE 4: y[b,2i]   += . (A = x)          grid (1024)         NTILE=64
// 256 threads, 8 warps (4m x 2n), warp tile 32 x NTILE/2.
// ---------------------------------------------------------------------------
template <int NTILE, int MODE>
__global__ __launch_bounds__(256) void hgemm(const float* __restrict__ gA,
                                             const unsigned short* __restrict__ gBhi,
                                             const unsigned short* __restrict__ gBlo,
                                             float* __restrict__ out) {
    extern __shared__ __align__(16) char smc[];
    // smem (bf16 elements, stride SSTRIDE): Ahi[128], Alo[128], Bhi[NTILE], Blo[NTILE]
    constexpr int A_ELE = 128 * SSTRIDE;
    constexpr int B_ELE = NTILE * SSTRIDE;
    unsigned short* sAhi = (unsigned short*)smc;
    unsigned short* sAlo = sAhi + A_ELE;
    unsigned short* sBhi = sAlo + A_ELE;
    unsigned short* sBlo = sBhi + B_ELE;
    const uint32_t aAhi = smem_u32(sAhi), aAlo = smem_u32(sAlo);
    const uint32_t aBhi = smem_u32(sBhi), aBlo = smem_u32(sBlo);

    const int t = threadIdx.x;
    const int lane = t & 31, w = t >> 5;

    // ---- stage A: fp32 -> (hi,lo) bf16 rows [m][k] ----
    {
        const float4* Atile = (const float4*)(gA + (size_t)blockIdx.x * (128 * 128));
#pragma unroll
        for (int j = 0; j < 16; j++) {
            const int f = j * 256 + t;
            const float4 v = Atile[f];
            const int row = f >> 5, c = (f & 31) * 4;
            unsigned short h0, l0, h1, l1, h2, l2, h3, l3;
            split_bf16(v.x, h0, l0);
            split_bf16(v.y, h1, l1);
            split_bf16(v.z, h2, l2);
            split_bf16(v.w, h3, l3);
            const unsigned long long hh =
                (unsigned long long)h0 | ((unsigned long long)h1 << 16) |
                ((unsigned long long)h2 << 32) | ((unsigned long long)h3 << 48);
            const unsigned long long ll =
                (unsigned long long)l0 | ((unsigned long long)l1 << 16) |
                ((unsigned long long)l2 << 32) | ((unsigned long long)l3 << 48);
            *(unsigned long long*)(sAhi + row * SSTRIDE + c) = hh;
            *(unsigned long long*)(sAlo + row * SSTRIDE + c) = ll;
        }
    }
    // ---- stage B: copy pre-split tiles [n][128] -> padded smem ----
    {
        const size_t boff = (MODE == 1) ? (size_t)blockIdx.y * (NTILE * 128) : 0;
        const uint4* sh = (const uint4*)(gBhi + boff);
        const uint4* sl = (const uint4*)(gBlo + boff);
#pragma unroll
        for (int j = 0; j < NTILE / 16; j++) {
            const int f = j * 256 + t;                  // uint4 id (8 bf16)
            const int row = f >> 4, c = (f & 15) * 8;
            *(uint4*)(sBhi + row * SSTRIDE + c) = sh[f];
            *(uint4*)(sBlo + row * SSTRIDE + c) = sl[f];
        }
    }
    __syncthreads();

    // ---- warp tiling ----
    const int wm = w & 3, wn = w >> 2;
    const int m0w = wm * 32, n0w = wn * (NTILE / 2);
    constexpr int NF = NTILE / 16;                      // n-frags per warp

    float acc[2][NF][4];
#pragma unroll
    for (int i = 0; i < 2; i++)
#pragma unroll
        for (int j = 0; j < NF; j++)
#pragma unroll
            for (int q = 0; q < 4; q++) acc[i][j][q] = 0.f;

    const int aRow = lane & 15, aCol = (lane >> 4) * 8;
    const int bRow = (lane & 7) + ((lane >> 4) << 3), bCol = ((lane >> 3) & 1) * 8;

#pragma unroll
    for (int ks = 0; ks < 8; ks++) {
        const int k0 = ks * 16;
        uint32_t ahi[2][4], alo[2][4];
#pragma unroll
        for (int mf = 0; mf < 2; mf++) {
            const uint32_t off =
                (uint32_t)(((m0w + mf * 16 + aRow) * SSTRIDE + k0 + aCol) * 2);
            ldsm4(aAhi + off, ahi[mf]);
            ldsm4(aAlo + off, alo[mf]);
        }
        uint32_t bhi[NF][2], blo[NF][2];
#pragma unroll
        for (int nf2 = 0; nf2 < NF / 2; nf2++) {
            const uint32_t off =
                (uint32_t)(((n0w + nf2 * 16 + bRow) * SSTRIDE + k0 + bCol) * 2);
            uint32_t r[4];
            ldsm4(aBhi + off, r);
            bhi[nf2 * 2][0] = r[0]; bhi[nf2 * 2][1] = r[1];
            bhi[nf2 * 2 + 1][0] = r[2]; bhi[nf2 * 2 + 1][1] = r[3];
            ldsm4(aBlo + off, r);
            blo[nf2 * 2][0] = r[0]; blo[nf2 * 2][1] = r[1];
            blo[nf2 * 2 + 1][0] = r[2]; blo[nf2 * 2 + 1][1] = r[3];
        }
#pragma unroll
        for (int mf = 0; mf < 2; mf++)
#pragma unroll
            for (int nf = 0; nf < NF; nf++) {
                mma16816(acc[mf][nf], ahi[mf], bhi[nf]);
                mma16816(acc[mf][nf], ahi[mf], blo[nf]);
                mma16816(acc[mf][nf], alo[mf], bhi[nf]);
            }
    }

    // ---- epilogue ----
#pragma unroll
    for (int mf = 0; mf < 2; mf++) {
#pragma unroll
        for (int half = 0; half < 2; half++) {
            const int rloc = m0w + mf * 16 + (lane >> 2) + half * 8;
            const int r = blockIdx.x * 128 + rloc;
            float* rowp;
            bool doacc = false, skip = false;
            if (MODE == 0) {
                rowp = out + (size_t)r * 128;
            } else if (MODE == 1) {
                rowp = out + (size_t)r * 4096 + blockIdx.y * 128;
            } else {
                const int b = r >> 11, i = r & (HT - 1);
                int trow;
                if (MODE == 2) trow = 2 * i + 1;
                else if (MODE == 3) {
                    trow = 2 * i + 2;
                    skip = ((i & (HCH - 1)) == (HCH - 1));
                } else trow = 2 * i;
                rowp = out + ((size_t)b * T_ + trow) * NOUT;
                doacc = true;
            }
            if (skip) continue;
#pragma unroll
            for (int nf = 0; nf < NF; nf++) {
                const int cc = n0w + nf * 8 + (lane & 3) * 2;
                float2 v = make_float2(acc[mf][nf][half * 2],
                                       acc[mf][nf][half * 2 + 1]);
                float* p = rowp + cc;
                if (doacc) {
                    float2 e = *(float2*)p;
                    v.x += e.x; v.y += e.y;
                }
                *(float2*)p = v;
            }
        }
    }
}

// ---------------------------------------------------------------------------
// Small kernels (R6/R7-verified)
// ---------------------------------------------------------------------------
__global__ __launch_bounds__(128) void matsq(const float* __restrict__ A,
                                             float* __restrict__ O) {
    const int r = blockIdx.x, u = threadIdx.x;
    __shared__ float row[U_];
    row[u] = A[r * U_ + u];
    __syncthreads();
    float a0 = 0.f, a1 = 0.f, a2 = 0.f, a3 = 0.f;
#pragma unroll
    for (int k = 0; k < U_; k += 4) {
        a0 = fmaf(row[k + 0], A[(k + 0) * U_ + u], a0);
        a1 = fmaf(row[k + 1], A[(k + 1) * U_ + u], a1);
        a2 = fmaf(row[k + 2], A[(k + 2) * U_ + u], a2);
        a3 = fmaf(row[k + 3], A[(k + 3) * U_ + u], a3);
    }
    O[r * U_ + u] = (a0 + a1) + (a2 + a3);
}

__global__ __launch_bounds__(128) void buildM(const float* __restrict__ KT,
                                              const float* __restrict__ A) {
    const int r = blockIdx.x, u = threadIdx.x;
    __shared__ float row[U_];
    row[u] = KT[r * U_ + u];
    __syncthreads();
    float a0 = 0.f, a1 = 0.f, a2 = 0.f, a3 = 0.f;
#pragma unroll
    for (int k = 0; k < U_; k += 4) {
        a0 = fmaf(row[k + 0], A[(k + 0) * U_ + u], a0);
        a1 = fmaf(row[k + 1], A[(k + 1) * U_ + u], a1);
        a2 = fmaf(row[k + 2], A[(k + 2) * U_ + u], a2);
        a3 = fmaf(row[k + 3], A[(k + 3) * U_ + u], a3);
    }
    g_M[r * U_ + u] = (a0 + a1) + (a2 + a3);
    g_M[(64 + r) * U_ + u] = row[u];
}

__global__ __launch_bounds__(64) void buildSmall(const float* __restrict__ KT,
                                                 const float* __restrict__ A,
                                                 const float* __restrict__ CyT) {
    const int bid = blockIdx.x, o = threadIdx.x;
    __shared__ float row[U_];
    const float* src = (bid < 64) ? (KT + (size_t)bid * U_)
                                  : (A + (size_t)(bid - 64) * U_);
    row[o] = src[o];
    row[o + 64] = src[o + 64];
    __syncthreads();
    float a0 = 0.f, a1 = 0.f, a2 = 0.f, a3 = 0.f;
#pragma unroll
    for (int k = 0; k < U_; k += 4) {
        a0 = fmaf(row[k + 0], CyT[(k + 0) * NOUT + o], a0);
        a1 = fmaf(row[k + 1], CyT[(k + 1) * NOUT + o], a1);
        a2 = fmaf(row[k + 2], CyT[(k + 2) * NOUT + o], a2);
        a3 = fmaf(row[k + 3], CyT[(k + 3) * NOUT + o], a3);
    }
    const float v = (a0 + a1) + (a2 + a3);
    if (bid < 64) g_KC[bid * NOUT + o] = v;
    else          g_ACyT[(bid - 64) * NOUT + o] = v;
}

// scan (R6-verified): e_i = Z_i + e_{i-1}@A2, 32 steps, 16 batches/CTA
__global__ __launch_bounds__(128, 2) void scan_kernel() {
    const int c = blockIdx.x, bg = blockIdx.y, u = threadIdx.x;
    const int b0 = bg * 16;
    __shared__ __align__(16) float s_sh[2][U_ * 16];

    float at2[U_];
#pragma unroll
    for (int k = 0; k < U_; k++) at2[k] = g_A2[k * U_ + u];
#pragma unroll
    for (int j = 0; j < 16; j++) s_sh[0][u * 16 + j] = 0.f;
    __syncthreads();

    const int i0 = c * HCH;
    float zc[16];
#pragma unroll
    for (int j = 0; j < 16; j++)
        zc[j] = g_Z[((size_t)(b0 + j) * HT + i0) * U_ + u];

    int p = 0;
#pragma unroll 1
    for (int it = 0; it < HCH; it++) {
        const int i = i0 + it;
        float zn[16];
        if (it < HCH - 1) {
#pragma unroll
            for (int j = 0; j < 16; j++)
                zn[j] = g_Z[((size_t)(b0 + j) * HT + i + 1) * U_ + u];
        } else {
#pragma unroll
            for (int j = 0; j < 16; j++) zn[j] = 0.f;
        }

        unsigned long long acc[8];
#pragma unroll
        for (int q = 0; q < 8; q++) acc[q] = pack2(zc[2 * q], zc[2 * q + 1]);

#pragma unroll
        for (int k = 0; k < U_; k++) {
            const unsigned long long av = dup2(at2[k]);
            const ulonglong2 s0 = *(const ulonglong2*)&s_sh[p][k * 16 + 0];
            const ulonglong2 s1 = *(const ulonglong2*)&s_sh[p][k * 16 + 4];
            const ulonglong2 s2 = *(const ulonglong2*)&s_sh[p][k * 16 + 8];
            const ulonglong2 s3 = *(const ulonglong2*)&s_sh[p][k * 16 + 12];
            acc[0] = ffma2(s0.x, av, acc[0]);
            acc[1] = ffma2(s0.y, av, acc[1]);
            acc[2] = ffma2(s1.x, av, acc[2]);
            acc[3] = ffma2(s1.y, av, acc[3]);
            acc[4] = ffma2(s2.x, av, acc[4]);
            acc[5] = ffma2(s2.y, av, acc[5]);
            acc[6] = ffma2(s3.x, av, acc[6]);
            acc[7] = ffma2(s3.y, av, acc[7]);
        }

        const int q = p ^ 1;
        float2 f0 = unpack2(acc[0]), f1 = unpack2(acc[1]);
        float2 f2 = unpack2(acc[2]), f3 = unpack2(acc[3]);
        float2 f4 = unpack2(acc[4]), f5 = unpack2(acc[5]);
        float2 f6 = unpack2(acc[6]), f7 = unpack2(acc[7]);
        {
            float4* dst = (float4*)&s_sh[q][u * 16];
            dst[0] = make_float4(f0.x, f0.y, f1.x, f1.y);
            dst[1] = make_float4(f2.x, f2.y, f3.x, f3.y);
            dst[2] = make_float4(f4.x, f4.y, f5.x, f5.y);
            dst[3] = make_float4(f6.x, f6.y, f7.x, f7.y);
        }
        g_S[((size_t)(b0 + 0)  * HT + i) * U_ + u] = f0.x;
        g_S[((size_t)(b0 + 1)  * HT + i) * U_ + u] = f0.y;
        g_S[((size_t)(b0 + 2)  * HT + i) * U_ + u] = f1.x;
        g_S[((size_t)(b0 + 3)  * HT + i) * U_ + u] = f1.y;
        g_S[((size_t)(b0 + 4)  * HT + i) * U_ + u] = f2.x;
        g_S[((size_t)(b0 + 5)  * HT + i) * U_ + u] = f2.y;
        g_S[((size_t)(b0 + 6)  * HT + i) * U_ + u] = f3.x;
        g_S[((size_t)(b0 + 7)  * HT + i) * U_ + u] = f3.y;
        g_S[((size_t)(b0 + 8)  * HT + i) * U_ + u] = f4.x;
        g_S[((size_t)(b0 + 9)  * HT + i) * U_ + u] = f4.y;
        g_S[((size_t)(b0 + 10) * HT + i) * U_ + u] = f5.x;
        g_S[((size_t)(b0 + 11) * HT + i) * U_ + u] = f5.y;
        g_S[((size_t)(b0 + 12) * HT + i) * U_ + u] = f6.x;
        g_S[((size_t)(b0 + 13) * HT + i) * U_ + u] = f6.y;
        g_S[((size_t)(b0 + 14) * HT + i) * U_ + u] = f7.x;
        g_S[((size_t)(b0 + 15) * HT + i) * U_ + u] = f7.y;
        __syncthreads();

        p = q;
#pragma unroll
        for (int j = 0; j < 16; j++) zc[j] = zn[j];
    }
}

__global__ __launch_bounds__(128) void pass2_kernel() {
    const int b = blockIdx.x, u = threadIdx.x;
    __shared__ float ss[2][U_];
    float m[U_];
#pragma unroll
    for (int k = 0; k < U_; k++) m[k] = g_A64[k * U_ + u];

    float su = 0.f;
    float e = g_S[((size_t)b * HT + (HCH - 1)) * U_ + u];
    ss[0][u] = 0.f;
    __syncthreads();

    int p = 0;
#pragma unroll 1
    for (int c = 0; c < CCH; c++) {
        g_carry[((size_t)b * CCH + c) * U_ + u] = su;
        float a0 = e, a1 = 0.f, a2 = 0.f, a3 = 0.f;
        if (c < CCH - 1)
            e = g_S[((size_t)b * HT + (c + 1) * HCH + (HCH - 1)) * U_ + u];
#pragma unroll
        for (int k = 0; k < U_; k += 4) {
            a0 = fmaf(ss[p][k + 0], m[k + 0], a0);
            a1 = fmaf(ss[p][k + 1], m[k + 1], a1);
            a2 = fmaf(ss[p][k + 2], m[k + 2], a2);
            a3 = fmaf(ss[p][k + 3], m[k + 3], a3);
        }
        su = (a0 + a1) + (a2 + a3);
        ss[p ^ 1][u] = su;
        __syncthreads();
        p ^= 1;
    }
}

__global__ __launch_bounds__(512) void wbuild(const float* __restrict__ A1,
                                              const float* __restrict__ CyT) {
    extern __shared__ float V[];
    float* cur = V;
    float* nxt = V + 8192;
    const int s = blockIdx.x;
    const int n = s + 1;
    const int tid = threadIdx.x;
    const int o = tid & 63, kg = tid >> 6;

    for (int i = tid; i < U_ * NOUT; i += 512) cur[i] = CyT[i];
    __syncthreads();

#pragma unroll 1
    for (int b = 0; b < 7; b++) {
        if (!((n >> b) & 1)) continue;
        const float* P = (b == 0) ? A1
                       : (b == 1) ? g_A2  : (b == 2) ? g_A4
                       : (b == 3) ? g_A8  : (b == 4) ? g_A16
                       : (b == 5) ? g_A32 : g_A64;
#pragma unroll 1
        for (int i = 0; i < 16; i++) {
            const int k = kg * 16 + i;
            float a0 = 0.f, a1 = 0.f, a2 = 0.f, a3 = 0.f;
#pragma unroll
            for (int m = 0; m < U_; m += 4) {
                a0 = fmaf(P[k * U_ + m + 0], cur[(m + 0) * 64 + o], a0);
                a1 = fmaf(P[k * U_ + m + 1], cur[(m + 1) * 64 + o], a1);
                a2 = fmaf(P[k * U_ + m + 2], cur[(m + 2) * 64 + o], a2);
                a3 = fmaf(P[k * U_ + m + 3], cur[(m + 3) * 64 + o], a3);
            }
            nxt[k * 64 + o] = (a0 + a1) + (a2 + a3);
        }
        __syncthreads();
        float* tmp = cur; cur = nxt; nxt = tmp;
    }

#pragma unroll 1
    for (int i = 0; i < 16; i++) {
        const int k = kg * 16 + i;
        g_Wt[(size_t)k * (LCH * NOUT) + s * 64 + o] = cur[k * 64 + o];
    }
}

// ---------------------------------------------------------------------------
// Launch.  #4 = hgemm<128,0> (zbuild) — the ncu-profiled slot.
// ---------------------------------------------------------------------------
extern "C" void kernel_launch(void* const* d_in, const int* in_sizes, int n_in,
                              void* d_out, int out_size) {
    const float* x   = (const float*)d_in[0];
    const float* AT  = (const float*)d_in[1];
    const float* KT  = (const float*)d_in[2];
    const float* CyT = (const float*)d_in[3];
    float* y = (float*)d_out;

    float *A2, *A4, *A8, *A16, *A32, *A64, *pM, *pWt, *pKC, *pACyT, *pZ, *pS, *pCar;
    unsigned short *MTh, *MTl, *WTh, *WTl, *CTh, *CTl, *ACTh, *ACTl, *KCTh, *KCTl;
    cudaGetSymbolAddress((void**)&A2,  g_A2);
    cudaGetSymbolAddress((void**)&A4,  g_A4);
    cudaGetSymbolAddress((void**)&A8,  g_A8);
    cudaGetSymbolAddress((void**)&A16, g_A16);
    cudaGetSymbolAddress((void**)&A32, g_A32);
    cudaGetSymbolAddress((void**)&A64, g_A64);
    cudaGetSymbolAddress((void**)&pM,  g_M);
    cudaGetSymbolAddress((void**)&pWt, g_Wt);
    cudaGetSymbolAddress((void**)&pKC, g_KC);
    cudaGetSymbolAddress((void**)&pACyT, g_ACyT);
    cudaGetSymbolAddress((void**)&pZ,  g_Z);
    cudaGetSymbolAddress((void**)&pS,  g_S);
    cudaGetSymbolAddress((void**)&pCar, g_carry);
    cudaGetSymbolAddress((void**)&MTh, g_MT_hi);  cudaGetSymbolAddress((void**)&MTl, g_MT_lo);
    cudaGetSymbolAddress((void**)&WTh, g_WT_hi);  cudaGetSymbolAddress((void**)&WTl, g_WT_lo);
    cudaGetSymbolAddress((void**)&CTh, g_CT_hi);  cudaGetSymbolAddress((void**)&CTl, g_CT_lo);
    cudaGetSymbolAddress((void**)&ACTh, g_ACT_hi); cudaGetSymbolAddress((void**)&ACTl, g_ACT_lo);
    cudaGetSymbolAddress((void**)&KCTh, g_KCT_hi); cudaGetSymbolAddress((void**)&KCTl, g_KCT_lo);

    // smem bytes: (2*A + 2*B) padded bf16
    const int SM128 = (2 * 128 * SSTRIDE + 2 * 128 * SSTRIDE) * 2;  // 139264
    const int SM64  = (2 * 128 * SSTRIDE + 2 * 64 * SSTRIDE) * 2;   // 104448
    cudaFuncSetAttribute(hgemm<128, 0>, cudaFuncAttributeMaxDynamicSharedMemorySize, SM128);
    cudaFuncSetAttribute(hgemm<128, 1>, cudaFuncAttributeMaxDynamicSharedMemorySize, SM128);
    cudaFuncSetAttribute(hgemm<64, 2>,  cudaFuncAttributeMaxDynamicSharedMemorySize, SM64);
    cudaFuncSetAttribute(hgemm<64, 3>,  cudaFuncAttributeMaxDynamicSharedMemorySize, SM64);
    cudaFuncSetAttribute(hgemm<64, 4>,  cudaFuncAttributeMaxDynamicSharedMemorySize, SM64);
    cudaFuncSetAttribute(wbuild, cudaFuncAttributeMaxDynamicSharedMemorySize, 65536);

    buildM<<<64, 128>>>(KT, AT);                               // 1
    matsq<<<128, 128>>>(AT, A2);                               // 2
    prepB<<<1, 256>>>(pM, 128, 128, MTh, MTl, 128);            // 3
    hgemm<128, 0><<<1024, 256, SM128>>>(x, MTh, MTl, pZ);      // 4  <- ncu
    scan_kernel<<<dim3(CCH, 4), 128>>>();                      // 5
    matsq<<<128, 128>>>(A2,  A4);                              // 6
    matsq<<<128, 128>>>(A4,  A8);                              // 7
    matsq<<<128, 128>>>(A8,  A16);                             // 8
    matsq<<<128, 128>>>(A16, A32);                             // 9
    matsq<<<128, 128>>>(A32, A64);                             // 10
    buildSmall<<<192, 64>>>(KT, AT, CyT);                      // 11
    prepB<<<1, 256>>>(CyT, 128, 64, CTh, CTl, 64);             // 12
    prepB<<<1, 256>>>(pACyT, 128, 64, ACTh, ACTl, 64);         // 13
    prepB<<<1, 256>>>(pKC, 64, 64, KCTh, KCTl, 64);            // 14
    pass2_kernel<<<B_, 128>>>();                               // 15
    wbuild<<<LCH, 512, 65536>>>(AT, CyT);                      // 16
    prepB<<<32, 256>>>(pWt, 128, 4096, WTh, WTl, 128);         // 17
    hgemm<128, 1><<<dim3(32, 32), 256, SM128>>>(pCar, WTh, WTl, y);  // 18 (writes y)
    hgemm<64, 4><<<1024, 256, SM64>>>(x,  KCTh, KCTl, y);      // 19 (+= even)
    hgemm<64, 2><<<1024, 256, SM64>>>(pS, CTh,  CTl,  y);      // 20 (+= odd)
    hgemm<64, 3><<<1024, 256, SM64>>>(pS, ACTh, ACTl, y);      // 21 (+= even+2)
}

// round 11
// speedup vs baseline: 2.8113x; 1.0121x over previous
#include <cuda_runtime.h>
#include <cuda_bf16.h>
#include <cstdint>

#define B_   64
#define T_   4096
#define NIN  64
#define U_   128
#define NOUT 64
#define CCH  64     // chunks (per batch)
#define LCH  64     // timesteps per chunk
#define HT   2048   // T/2 : pair count per batch
#define HCH  32     // odd states per chunk

#define SSTRIDE 136  // padded bf16 row stride in smem (elements)

// ---------------------------------------------------------------------------
// Static device scratch
// ---------------------------------------------------------------------------
__device__ float g_Z[B_ * HT * U_];       // 64 MB
__device__ float g_S[B_ * HT * U_];       // 64 MB
__device__ float g_carry[B_ * CCH * U_];
__device__ float g_M[U_ * U_];            // stacked [[KT@A],[KT]]  ([k][n])
__device__ float g_KC[NIN * NOUT];        // KT@CyT  [64k][64n]
__device__ float g_ACyT[U_ * NOUT];       // A@CyT   [128k][64n]
__device__ float g_A2[U_ * U_], g_A4[U_ * U_], g_A8[U_ * U_];
__device__ float g_A16[U_ * U_], g_A32[U_ * U_], g_A64[U_ * U_];

// Pre-split bf16 B tiles, per-tile layout [n_local][k] (k contiguous, 128)
__device__ __align__(16) unsigned short g_MT_hi[128 * 128],  g_MT_lo[128 * 128];
__device__ __align__(16) unsigned short g_WT_hi[32 * 128 * 128], g_WT_lo[32 * 128 * 128];
__device__ __align__(16) unsigned short g_YB_hi[128 * 128],  g_YB_lo[128 * 128]; // [CyT|ACyT]
__device__ __align__(16) unsigned short g_KCT_hi[64 * 128],  g_KCT_lo[64 * 128];

// ---------------------------------------------------------------------------
// f32x2 helpers (scan path)
// ---------------------------------------------------------------------------
__device__ __forceinline__ unsigned long long ffma2(unsigned long long a,
                                                    unsigned long long b,
                                                    unsigned long long c) {
    unsigned long long d;
    asm("fma.rn.f32x2 %0, %1, %2, %3;" : "=l"(d) : "l"(a), "l"(b), "l"(c));
    return d;
}
__device__ __forceinline__ unsigned long long dup2(float v) {
    unsigned long long r;
    asm("mov.b64 %0, {%1, %1};" : "=l"(r) : "f"(v));
    return r;
}
__device__ __forceinline__ unsigned long long pack2(float x, float y) {
    unsigned long long r;
    asm("mov.b64 %0, {%1, %2};" : "=l"(r) : "f"(x), "f"(y));
    return r;
}
__device__ __forceinline__ float2 unpack2(unsigned long long v) {
    float2 f;
    asm("mov.b64 {%0, %1}, %2;" : "=f"(f.x), "=f"(f.y) : "l"(v));
    return f;
}

// ---------------------------------------------------------------------------
// mma.sync / ldmatrix helpers (base ISA, sm_80+)
// ---------------------------------------------------------------------------
__device__ __forceinline__ uint32_t smem_u32(const void* p) {
    uint32_t a;
    asm("{ .reg .u64 t; cvta.to.shared.u64 t, %1; cvt.u32.u64 %0, t; }"
        : "=r"(a) : "l"(p));
    return a;
}

__device__ __forceinline__ void ldsm4(uint32_t addr, uint32_t r[4]) {
    asm volatile("ldmatrix.sync.aligned.m8n8.x4.shared.b16 {%0,%1,%2,%3}, [%4];"
                 : "=r"(r[0]), "=r"(r[1]), "=r"(r[2]), "=r"(r[3]) : "r"(addr));
}

__device__ __forceinline__ void mma16816(float c[4], const uint32_t a[4],
                                         const uint32_t b[2]) {
    asm volatile(
        "mma.sync.aligned.m16n8k16.row.col.f32.bf16.bf16.f32 "
        "{%0,%1,%2,%3}, {%4,%5,%6,%7}, {%8,%9}, {%0,%1,%2,%3};"
        : "+f"(c[0]), "+f"(c[1]), "+f"(c[2]), "+f"(c[3])
        : "r"(a[0]), "r"(a[1]), "r"(a[2]), "r"(a[3]), "r"(b[0]), "r"(b[1]));
}

__device__ __forceinline__ void split_bf16(float v, unsigned short& h, unsigned short& l) {
    __nv_bfloat16 hb = __float2bfloat16(v);
    float r = v - __bfloat162float(hb);
    __nv_bfloat16 lb = __float2bfloat16(r);
    h = *reinterpret_cast<unsigned short*>(&hb);
    l = *reinterpret_cast<unsigned short*>(&lb);
}

// ---------------------------------------------------------------------------
// prepB: split a fp32 [K][N] matrix (row stride Nsrc) into bf16 hi/lo tiles
// of ntileRows x 128 (k), per-tile layout [n_local][k].  grid = ntiles.
// (only used for small matrices now: M, CyT, ACyT, KC)
// ---------------------------------------------------------------------------
__global__ __launch_bounds__(256) void prepB(const float* __restrict__ src,
                                             int Ksrc, int Nsrc,
                                             unsigned short* __restrict__ dhi,
                                             unsigned short* __restrict__ dlo,
                                             int ntileRows) {
    const int nt = blockIdx.x;
    const int elems = ntileRows * 128;
    unsigned short* th = dhi + (size_t)nt * elems;
    unsigned short* tl = dlo + (size_t)nt * elems;
    for (int idx = threadIdx.x; idx < elems; idx += 256) {
        const int nl = idx >> 7, k = idx & 127;
        const int n = nt * ntileRows + nl;
        float v = (k < Ksrc) ? src[(size_t)k * Nsrc + n] : 0.f;
        unsigned short h, l;
        split_bf16(v, h, l);
        th[nl * 128 + k] = h;
        tl[nl * 128 + k] = l;
    }
}

// ---------------------------------------------------------------------------
// hgemm: D[128, NTILE] = A[128,128] @ B^T via mma.sync split-bf16.
// MODE 0: out = g_Z rows (write)           grid (1024)         NTILE=128
// MODE 1: out = y, col base by*128 (write)  grid (32 mx, 32 by) NTILE=128
// MODE 4: y[b,2i]   += . (A = x, B = KC)    grid (1024)         NTILE=64
// MODE 5: merged: n<64 -> y[2i+1] += S@CyT ; n>=64 -> y[2i+2] += S@ACyT
//         (skip chunk-last i for n>=64)     grid (1024)         NTILE=128
// 256 threads, 8 warps (4m x 2n), warp tile 32 x NTILE/2.
// ---------------------------------------------------------------------------
template <int NTILE, int MODE>
__global__ __launch_bounds__(256) void hgemm(const float* __restrict__ gA,
                                             const unsigned short* __restrict__ gBhi,
                                             const unsigned short* __restrict__ gBlo,
                                             float* __restrict__ out) {
    extern __shared__ __align__(16) char smc[];
    constexpr int A_ELE = 128 * SSTRIDE;
    constexpr int B_ELE = NTILE * SSTRIDE;
    unsigned short* sAhi = (unsigned short*)smc;
    unsigned short* sAlo = sAhi + A_ELE;
    unsigned short* sBhi = sAlo + A_ELE;
    unsigned short* sBlo = sBhi + B_ELE;
    const uint32_t aAhi = smem_u32(sAhi), aAlo = smem_u32(sAlo);
    const uint32_t aBhi = smem_u32(sBhi), aBlo = smem_u32(sBlo);

    const int t = threadIdx.x;
    const int lane = t & 31, w = t >> 5;

    // ---- stage A: fp32 -> (hi,lo) bf16 rows [m][k] ----
    {
        const float4* Atile = (const float4*)(gA + (size_t)blockIdx.x * (128 * 128));
#pragma unroll
        for (int j = 0; j < 16; j++) {
            const int f = j * 256 + t;
            const float4 v = Atile[f];
            const int row = f >> 5, c = (f & 31) * 4;
            unsigned short h0, l0, h1, l1, h2, l2, h3, l3;
            split_bf16(v.x, h0, l0);
            split_bf16(v.y, h1, l1);
            split_bf16(v.z, h2, l2);
            split_bf16(v.w, h3, l3);
            const unsigned long long hh =
                (unsigned long long)h0 | ((unsigned long long)h1 << 16) |
                ((unsigned long long)h2 << 32) | ((unsigned long long)h3 << 48);
            const unsigned long long ll =
                (unsigned long long)l0 | ((unsigned long long)l1 << 16) |
                ((unsigned long long)l2 << 32) | ((unsigned long long)l3 << 48);
            *(unsigned long long*)(sAhi + row * SSTRIDE + c) = hh;
            *(unsigned long long*)(sAlo + row * SSTRIDE + c) = ll;
        }
    }
    // ---- stage B: copy pre-split tiles [n][128] -> padded smem ----
    {
        const size_t boff = (MODE == 1) ? (size_t)blockIdx.y * (NTILE * 128) : 0;
        const uint4* sh = (const uint4*)(gBhi + boff);
        const uint4* sl = (const uint4*)(gBlo + boff);
#pragma unroll
        for (int j = 0; j < NTILE / 16; j++) {
            const int f = j * 256 + t;                  // uint4 id (8 bf16)
            const int row = f >> 4, c = (f & 15) * 8;
            *(uint4*)(sBhi + row * SSTRIDE + c) = sh[f];
            *(uint4*)(sBlo + row * SSTRIDE + c) = sl[f];
        }
    }
    __syncthreads();

    // ---- warp tiling ----
    const int wm = w & 3, wn = w >> 2;
    const int m0w = wm * 32, n0w = wn * (NTILE / 2);
    constexpr int NF = NTILE / 16;                      // n-frags per warp

    float acc[2][NF][4];
#pragma unroll
    for (int i = 0; i < 2; i++)
#pragma unroll
        for (int j = 0; j < NF; j++)
#pragma unroll
            for (int q = 0; q < 4; q++) acc[i][j][q] = 0.f;

    const int aRow = lane & 15, aCol = (lane >> 4) * 8;
    const int bRow = (lane & 7) + ((lane >> 4) << 3), bCol = ((lane >> 3) & 1) * 8;

#pragma unroll
    for (int ks = 0; ks < 8; ks++) {
        const int k0 = ks * 16;
        uint32_t ahi[2][4], alo[2][4];
#pragma unroll
        for (int mf = 0; mf < 2; mf++) {
            const uint32_t off =
                (uint32_t)(((m0w + mf * 16 + aRow) * SSTRIDE + k0 + aCol) * 2);
            ldsm4(aAhi + off, ahi[mf]);
            ldsm4(aAlo + off, alo[mf]);
        }
        uint32_t bhi[NF][2], blo[NF][2];
#pragma unroll
        for (int nf2 = 0; nf2 < NF / 2; nf2++) {
            const uint32_t off =
                (uint32_t)(((n0w + nf2 * 16 + bRow) * SSTRIDE + k0 + bCol) * 2);
            uint32_t r[4];
            ldsm4(aBhi + off, r);
            bhi[nf2 * 2][0] = r[0]; bhi[nf2 * 2][1] = r[1];
            bhi[nf2 * 2 + 1][0] = r[2]; bhi[nf2 * 2 + 1][1] = r[3];
            ldsm4(aBlo + off, r);
            blo[nf2 * 2][0] = r[0]; blo[nf2 * 2][1] = r[1];
            blo[nf2 * 2 + 1][0] = r[2]; blo[nf2 * 2 + 1][1] = r[3];
        }
#pragma unroll
        for (int mf = 0; mf < 2; mf++)
#pragma unroll
            for (int nf = 0; nf < NF; nf++) {
                mma16816(acc[mf][nf], ahi[mf], bhi[nf]);
                mma16816(acc[mf][nf], ahi[mf], blo[nf]);
                mma16816(acc[mf][nf], alo[mf], bhi[nf]);
            }
    }

    // ---- epilogue ----
#pragma unroll
    for (int mf = 0; mf < 2; mf++) {
#pragma unroll
        for (int half = 0; half < 2; half++) {
            const int rloc = m0w + mf * 16 + (lane >> 2) + half * 8;
            const int r = blockIdx.x * 128 + rloc;

            if (MODE == 5) {
                const int b = r >> 11, i = r & (HT - 1);
                const bool lastI = ((i & (HCH - 1)) == (HCH - 1));
                float* base1 = out + ((size_t)b * T_ + 2 * i + 1) * NOUT;
                float* base2 = out + ((size_t)b * T_ + 2 * i + 2) * NOUT;
#pragma unroll
                for (int nf = 0; nf < NF; nf++) {
                    const int n = n0w + nf * 8 + (lane & 3) * 2;
                    float* p;
                    if (n < 64) p = base1 + n;
                    else { if (lastI) continue; p = base2 + (n - 64); }
                    float2 v = make_float2(acc[mf][nf][half * 2],
                                           acc[mf][nf][half * 2 + 1]);
                    float2 e = *(float2*)p;
                    v.x += e.x; v.y += e.y;
                    *(float2*)p = v;
                }
                continue;
            }

            float* rowp;
            bool doacc = false;
            if (MODE == 0) {
                rowp = out + (size_t)r * 128;
            } else if (MODE == 1) {
                rowp = out + (size_t)r * 4096 + blockIdx.y * 128;
            } else {  // MODE 4
                const int b = r >> 11, i = r & (HT - 1);
                rowp = out + ((size_t)b * T_ + 2 * i) * NOUT;
                doacc = true;
            }
#pragma unroll
            for (int nf = 0; nf < NF; nf++) {
                const int cc = n0w + nf * 8 + (lane & 3) * 2;
                float2 v = make_float2(acc[mf][nf][half * 2],
                                       acc[mf][nf][half * 2 + 1]);
                float* p = rowp + cc;
                if (doacc) {
                    float2 e = *(float2*)p;
                    v.x += e.x; v.y += e.y;
                }
                *(float2*)p = v;
            }
        }
    }
}

// ---------------------------------------------------------------------------
// Small kernels (R6/R7-verified)
// ---------------------------------------------------------------------------
__global__ __launch_bounds__(128) void matsq(const float* __restrict__ A,
                                             float* __restrict__ O) {
    const int r = blockIdx.x, u = threadIdx.x;
    __shared__ float row[U_];
    row[u] = A[r * U_ + u];
    __syncthreads();
    float a0 = 0.f, a1 = 0.f, a2 = 0.f, a3 = 0.f;
#pragma unroll
    for (int k = 0; k < U_; k += 4) {
        a0 = fmaf(row[k + 0], A[(k + 0) * U_ + u], a0);
        a1 = fmaf(row[k + 1], A[(k + 1) * U_ + u], a1);
        a2 = fmaf(row[k + 2], A[(k + 2) * U_ + u], a2);
        a3 = fmaf(row[k + 3], A[(k + 3) * U_ + u], a3);
    }
    O[r * U_ + u] = (a0 + a1) + (a2 + a3);
}

__global__ __launch_bounds__(128) void buildM(const float* __restrict__ KT,
                                              const float* __restrict__ A) {
    const int r = blockIdx.x, u = threadIdx.x;
    __shared__ float row[U_];
    row[u] = KT[r * U_ + u];
    __syncthreads();
    float a0 = 0.f, a1 = 0.f, a2 = 0.f, a3 = 0.f;
#pragma unroll
    for (int k = 0; k < U_; k += 4) {
        a0 = fmaf(row[k + 0], A[(k + 0) * U_ + u], a0);
        a1 = fmaf(row[k + 1], A[(k + 1) * U_ + u], a1);
        a2 = fmaf(row[k + 2], A[(k + 2) * U_ + u], a2);
        a3 = fmaf(row[k + 3], A[(k + 3) * U_ + u], a3);
    }
    g_M[r * U_ + u] = (a0 + a1) + (a2 + a3);
    g_M[(64 + r) * U_ + u] = row[u];
}

__global__ __launch_bounds__(64) void buildSmall(const float* __restrict__ KT,
                                                 const float* __restrict__ A,
                                                 const float* __restrict__ CyT) {
    const int bid = blockIdx.x, o = threadIdx.x;
    __shared__ float row[U_];
    const float* src = (bid < 64) ? (KT + (size_t)bid * U_)
                                  : (A + (size_t)(bid - 64) * U_);
    row[o] = src[o];
    row[o + 64] = src[o + 64];
    __syncthreads();
    float a0 = 0.f, a1 = 0.f, a2 = 0.f, a3 = 0.f;
#pragma unroll
    for (int k = 0; k < U_; k += 4) {
        a0 = fmaf(row[k + 0], CyT[(k + 0) * NOUT + o], a0);
        a1 = fmaf(row[k + 1], CyT[(k + 1) * NOUT + o], a1);
        a2 = fmaf(row[k + 2], CyT[(k + 2) * NOUT + o], a2);
        a3 = fmaf(row[k + 3], CyT[(k + 3) * NOUT + o], a3);
    }
    const float v = (a0 + a1) + (a2 + a3);
    if (bid < 64) g_KC[bid * NOUT + o] = v;
    else          g_ACyT[(bid - 64) * NOUT + o] = v;
}

// scan (R6-verified): e_i = Z_i + e_{i-1}@A2, 32 steps, 16 batches/CTA
__global__ __launch_bounds__(128, 2) void scan_kernel() {
    const int c = blockIdx.x, bg = blockIdx.y, u = threadIdx.x;
    const int b0 = bg * 16;
    __shared__ __align__(16) float s_sh[2][U_ * 16];

    float at2[U_];
#pragma unroll
    for (int k = 0; k < U_; k++) at2[k] = g_A2[k * U_ + u];
#pragma unroll
    for (int j = 0; j < 16; j++) s_sh[0][u * 16 + j] = 0.f;
    __syncthreads();

    const int i0 = c * HCH;
    float zc[16];
#pragma unroll
    for (int j = 0; j < 16; j++)
        zc[j] = g_Z[((size_t)(b0 + j) * HT + i0) * U_ + u];

    int p = 0;
#pragma unroll 1
    for (int it = 0; it < HCH; it++) {
        const int i = i0 + it;
        float zn[16];
        if (it < HCH - 1) {
#pragma unroll
            for (int j = 0; j < 16; j++)
                zn[j] = g_Z[((size_t)(b0 + j) * HT + i + 1) * U_ + u];
        } else {
#pragma unroll
            for (int j = 0; j < 16; j++) zn[j] = 0.f;
        }

        unsigned long long acc[8];
#pragma unroll
        for (int q = 0; q < 8; q++) acc[q] = pack2(zc[2 * q], zc[2 * q + 1]);

#pragma unroll
        for (int k = 0; k < U_; k++) {
            const unsigned long long av = dup2(at2[k]);
            const ulonglong2 s0 = *(const ulonglong2*)&s_sh[p][k * 16 + 0];
            const ulonglong2 s1 = *(const ulonglong2*)&s_sh[p][k * 16 + 4];
            const ulonglong2 s2 = *(const ulonglong2*)&s_sh[p][k * 16 + 8];
            const ulonglong2 s3 = *(const ulonglong2*)&s_sh[p][k * 16 + 12];
            acc[0] = ffma2(s0.x, av, acc[0]);
            acc[1] = ffma2(s0.y, av, acc[1]);
            acc[2] = ffma2(s1.x, av, acc[2]);
            acc[3] = ffma2(s1.y, av, acc[3]);
            acc[4] = ffma2(s2.x, av, acc[4]);
            acc[5] = ffma2(s2.y, av, acc[5]);
            acc[6] = ffma2(s3.x, av, acc[6]);
            acc[7] = ffma2(s3.y, av, acc[7]);
        }

        const int q = p ^ 1;
        float2 f0 = unpack2(acc[0]), f1 = unpack2(acc[1]);
        float2 f2 = unpack2(acc[2]), f3 = unpack2(acc[3]);
        float2 f4 = unpack2(acc[4]), f5 = unpack2(acc[5]);
        float2 f6 = unpack2(acc[6]), f7 = unpack2(acc[7]);
        {
            float4* dst = (float4*)&s_sh[q][u * 16];
            dst[0] = make_float4(f0.x, f0.y, f1.x, f1.y);
            dst[1] = make_float4(f2.x, f2.y, f3.x, f3.y);
            dst[2] = make_float4(f4.x, f4.y, f5.x, f5.y);
            dst[3] = make_float4(f6.x, f6.y, f7.x, f7.y);
        }
        g_S[((size_t)(b0 + 0)  * HT + i) * U_ + u] = f0.x;
        g_S[((size_t)(b0 + 1)  * HT + i) * U_ + u] = f0.y;
        g_S[((size_t)(b0 + 2)  * HT + i) * U_ + u] = f1.x;
        g_S[((size_t)(b0 + 3)  * HT + i) * U_ + u] = f1.y;
        g_S[((size_t)(b0 + 4)  * HT + i) * U_ + u] = f2.x;
        g_S[((size_t)(b0 + 5)  * HT + i) * U_ + u] = f2.y;
        g_S[((size_t)(b0 + 6)  * HT + i) * U_ + u] = f3.x;
        g_S[((size_t)(b0 + 7)  * HT + i) * U_ + u] = f3.y;
        g_S[((size_t)(b0 + 8)  * HT + i) * U_ + u] = f4.x;
        g_S[((size_t)(b0 + 9)  * HT + i) * U_ + u] = f4.y;
        g_S[((size_t)(b0 + 10) * HT + i) * U_ + u] = f5.x;
        g_S[((size_t)(b0 + 11) * HT + i) * U_ + u] = f5.y;
        g_S[((size_t)(b0 + 12) * HT + i) * U_ + u] = f6.x;
        g_S[((size_t)(b0 + 13) * HT + i) * U_ + u] = f6.y;
        g_S[((size_t)(b0 + 14) * HT + i) * U_ + u] = f7.x;
        g_S[((size_t)(b0 + 15) * HT + i) * U_ + u] = f7.y;
        __syncthreads();

        p = q;
#pragma unroll
        for (int j = 0; j < 16; j++) zc[j] = zn[j];
    }
}

__global__ __launch_bounds__(128) void pass2_kernel() {
    const int b = blockIdx.x, u = threadIdx.x;
    __shared__ float ss[2][U_];
    float m[U_];
#pragma unroll
    for (int k = 0; k < U_; k++) m[k] = g_A64[k * U_ + u];

    float su = 0.f;
    float e = g_S[((size_t)b * HT + (HCH - 1)) * U_ + u];
    ss[0][u] = 0.f;
    __syncthreads();

    int p = 0;
#pragma unroll 1
    for (int c = 0; c < CCH; c++) {
        g_carry[((size_t)b * CCH + c) * U_ + u] = su;
        float a0 = e, a1 = 0.f, a2 = 0.f, a3 = 0.f;
        if (c < CCH - 1)
            e = g_S[((size_t)b * HT + (c + 1) * HCH + (HCH - 1)) * U_ + u];
#pragma unroll
        for (int k = 0; k < U_; k += 4) {
            a0 = fmaf(ss[p][k + 0], m[k + 0], a0);
            a1 = fmaf(ss[p][k + 1], m[k + 1], a1);
            a2 = fmaf(ss[p][k + 2], m[k + 2], a2);
            a3 = fmaf(ss[p][k + 3], m[k + 3], a3);
        }
        su = (a0 + a1) + (a2 + a3);
        ss[p ^ 1][u] = su;
        __syncthreads();
        p ^= 1;
    }
}

// ---------------------------------------------------------------------------
// wbuild: CTA s computes W[s] = A^(s+1)@CyT via binary power chain, then
// writes split bf16 hi/lo DIRECTLY into g_WT_hi/lo tiles (coalesced along k).
// Tile layout matches hgemm<128,1>: tile by = s>>1, n_local = (s&1)*64+o.
// ---------------------------------------------------------------------------
__global__ __launch_bounds__(512) void wbuild(const float* __restrict__ A1,
                                              const float* __restrict__ CyT) {
    extern __shared__ float V[];
    float* cur = V;
    float* nxt = V + 8192;
    const int s = blockIdx.x;
    const int n = s + 1;
    const int tid = threadIdx.x;
    const int o = tid & 63, kg = tid >> 6;

    for (int i = tid; i < U_ * NOUT; i += 512) cur[i] = CyT[i];
    __syncthreads();

#pragma unroll 1
    for (int b = 0; b < 7; b++) {
        if (!((n >> b) & 1)) continue;
        const float* P = (b == 0) ? A1
                       : (b == 1) ? g_A2  : (b == 2) ? g_A4
                       : (b == 3) ? g_A8  : (b == 4) ? g_A16
                       : (b == 5) ? g_A32 : g_A64;
#pragma unroll 1
        for (int i = 0; i < 16; i++) {
            const int k = kg * 16 + i;
            float a0 = 0.f, a1 = 0.f, a2 = 0.f, a3 = 0.f;
#pragma unroll
            for (int m = 0; m < U_; m += 4) {
                a0 = fmaf(P[k * U_ + m + 0], cur[(m + 0) * 64 + o], a0);
                a1 = fmaf(P[k * U_ + m + 1], cur[(m + 1) * 64 + o], a1);
                a2 = fmaf(P[k * U_ + m + 2], cur[(m + 2) * 64 + o], a2);
                a3 = fmaf(P[k * U_ + m + 3], cur[(m + 3) * 64 + o], a3);
            }
            nxt[k * 64 + o] = (a0 + a1) + (a2 + a3);
        }
        __syncthreads();
        float* tmp = cur; cur = nxt; nxt = tmp;
    }

    // direct split write: idx = oo*128 + k, k fast -> coalesced gmem stores
    {
        unsigned short* th = g_WT_hi + (size_t)(s >> 1) * 16384;
        unsigned short* tl = g_WT_lo + (size_t)(s >> 1) * 16384;
        const int nbase = (s & 1) * 64;
#pragma unroll 1
        for (int idx = tid; idx < 8192; idx += 512) {
            const int k = idx & 127, oo = idx >> 7;
            unsigned short h, l;
            split_bf16(cur[k * 64 + oo], h, l);
            th[(nbase + oo) * 128 + k] = h;
            tl[(nbase + oo) * 128 + k] = l;
        }
    }
}

// ---------------------------------------------------------------------------
// Launch.  #4 = hgemm<128,0> (zbuild) — the ncu-profiled slot.
// ---------------------------------------------------------------------------
extern "C" void kernel_launch(void* const* d_in, const int* in_sizes, int n_in,
                              void* d_out, int out_size) {
    const float* x   = (const float*)d_in[0];
    const float* AT  = (const float*)d_in[1];
    const float* KT  = (const float*)d_in[2];
    const float* CyT = (const float*)d_in[3];
    float* y = (float*)d_out;

    float *A2, *A4, *A8, *A16, *A32, *A64, *pM, *pKC, *pACyT, *pZ, *pS, *pCar;
    unsigned short *MTh, *MTl, *WTh, *WTl, *YBh, *YBl, *KCTh, *KCTl;
    cudaGetSymbolAddress((void**)&A2,  g_A2);
    cudaGetSymbolAddress((void**)&A4,  g_A4);
    cudaGetSymbolAddress((void**)&A8,  g_A8);
    cudaGetSymbolAddress((void**)&A16, g_A16);
    cudaGetSymbolAddress((void**)&A32, g_A32);
    cudaGetSymbolAddress((void**)&A64, g_A64);
    cudaGetSymbolAddress((void**)&pM,  g_M);
    cudaGetSymbolAddress((void**)&pKC, g_KC);
    cudaGetSymbolAddress((void**)&pACyT, g_ACyT);
    cudaGetSymbolAddress((void**)&pZ,  g_Z);
    cudaGetSymbolAddress((void**)&pS,  g_S);
    cudaGetSymbolAddress((void**)&pCar, g_carry);
    cudaGetSymbolAddress((void**)&MTh, g_MT_hi);  cudaGetSymbolAddress((void**)&MTl, g_MT_lo);
    cudaGetSymbolAddress((void**)&WTh, g_WT_hi);  cudaGetSymbolAddress((void**)&WTl, g_WT_lo);
    cudaGetSymbolAddress((void**)&YBh, g_YB_hi);  cudaGetSymbolAddress((void**)&YBl, g_YB_lo);
    cudaGetSymbolAddress((void**)&KCTh, g_KCT_hi); cudaGetSymbolAddress((void**)&KCTl, g_KCT_lo);

    const int SM128 = (2 * 128 * SSTRIDE + 2 * 128 * SSTRIDE) * 2;  // 139264
    const int SM64  = (2 * 128 * SSTRIDE + 2 * 64 * SSTRIDE) * 2;   // 104448
    cudaFuncSetAttribute(hgemm<128, 0>, cudaFuncAttributeMaxDynamicSharedMemorySize, SM128);
    cudaFuncSetAttribute(hgemm<128, 1>, cudaFuncAttributeMaxDynamicSharedMemorySize, SM128);
    cudaFuncSetAttribute(hgemm<128, 5>, cudaFuncAttributeMaxDynamicSharedMemorySize, SM128);
    cudaFuncSetAttribute(hgemm<64, 4>,  cudaFuncAttributeMaxDynamicSharedMemorySize, SM64);
    cudaFuncSetAttribute(wbuild, cudaFuncAttributeMaxDynamicSharedMemorySize, 65536);

    buildM<<<64, 128>>>(KT, AT);                               // 1
    matsq<<<128, 128>>>(AT, A2);                               // 2
    prepB<<<1, 256>>>(pM, 128, 128, MTh, MTl, 128);            // 3
    hgemm<128, 0><<<1024, 256, SM128>>>(x, MTh, MTl, pZ);      // 4  <- ncu
    scan_kernel<<<dim3(CCH, 4), 128>>>();                      // 5
    matsq<<<128, 128>>>(A2,  A4);                              // 6
    matsq<<<128, 128>>>(A4,  A8);                              // 7
    matsq<<<128, 128>>>(A8,  A16);                             // 8
    matsq<<<128, 128>>>(A16, A32);                             // 9
    matsq<<<128, 128>>>(A32, A64);                             // 10
    buildSmall<<<192, 64>>>(KT, AT, CyT);                      // 11
    prepB<<<1, 256>>>(CyT, 128, 64, YBh, YBl, 64);             // 12 (YB rows 0-63)
    prepB<<<1, 256>>>(pACyT, 128, 64, YBh + 64 * 128, YBl + 64 * 128, 64); // 13
    prepB<<<1, 256>>>(pKC, 64, 64, KCTh, KCTl, 64);            // 14
    pass2_kernel<<<B_, 128>>>();                               // 15
    wbuild<<<LCH, 512, 65536>>>(AT, CyT);                      // 16 (writes WT direct)
    hgemm<128, 1><<<dim3(32, 32), 256, SM128>>>(pCar, WTh, WTl, y);  // 17 (writes y)
    hgemm<64, 4><<<1024, 256, SM64>>>(x,  KCTh, KCTl, y);      // 18 (+= even)
    hgemm<128, 5><<<1024, 256, SM128>>>(pS, YBh, YBl, y);      // 19 (+= odd & even+2)
}

// round 13
// speedup vs baseline: 3.0074x; 1.0698x over previous
#include <cuda_runtime.h>
#include <cuda_bf16.h>
#include <cstdint>

#define B_   64
#define T_   4096
#define NIN  64
#define U_   128
#define NOUT 64
#define CCH  64     // chunks (per batch)
#define LCH  64     // timesteps per chunk
#define HT   2048   // T/2 : pair count per batch
#define HCH  32     // odd states per chunk

#define SSTRIDE 136  // padded bf16 row stride in smem (elements)
#define MROWS   64   // hgemm M-tile rows (was 128; 64 -> 2 CTAs/SM)

// ---------------------------------------------------------------------------
// Static device scratch
// ---------------------------------------------------------------------------
__device__ float g_Z[B_ * HT * U_];       // 64 MB
__device__ float g_S[B_ * HT * U_];       // 64 MB
__device__ float g_carry[B_ * CCH * U_];
__device__ float g_M[U_ * U_];            // stacked [[KT@A],[KT]]  ([k][n])
__device__ float g_KC[NIN * NOUT];        // KT@CyT  [64k][64n]
__device__ float g_ACyT[U_ * NOUT];       // A@CyT   [128k][64n]
__device__ float g_A2[U_ * U_], g_A4[U_ * U_], g_A8[U_ * U_];
__device__ float g_A16[U_ * U_], g_A32[U_ * U_], g_A64[U_ * U_];

// Pre-split bf16 B tiles, per-tile layout [n_local][k] (k contiguous, 128)
__device__ __align__(16) unsigned short g_MT_hi[128 * 128],  g_MT_lo[128 * 128];
__device__ __align__(16) unsigned short g_WT_hi[32 * 128 * 128], g_WT_lo[32 * 128 * 128];
__device__ __align__(16) unsigned short g_YB_hi[128 * 128],  g_YB_lo[128 * 128]; // [CyT|ACyT]
__device__ __align__(16) unsigned short g_KCT_hi[64 * 128],  g_KCT_lo[64 * 128];

// ---------------------------------------------------------------------------
// f32x2 helpers (scan path)
// ---------------------------------------------------------------------------
__device__ __forceinline__ unsigned long long ffma2(unsigned long long a,
                                                    unsigned long long b,
                                                    unsigned long long c) {
    unsigned long long d;
    asm("fma.rn.f32x2 %0, %1, %2, %3;" : "=l"(d) : "l"(a), "l"(b), "l"(c));
    return d;
}
__device__ __forceinline__ unsigned long long dup2(float v) {
    unsigned long long r;
    asm("mov.b64 %0, {%1, %1};" : "=l"(r) : "f"(v));
    return r;
}
__device__ __forceinline__ unsigned long long pack2(float x, float y) {
    unsigned long long r;
    asm("mov.b64 %0, {%1, %2};" : "=l"(r) : "f"(x), "f"(y));
    return r;
}
__device__ __forceinline__ float2 unpack2(unsigned long long v) {
    float2 f;
    asm("mov.b64 {%0, %1}, %2;" : "=f"(f.x), "=f"(f.y) : "l"(v));
    return f;
}

// ---------------------------------------------------------------------------
// mma.sync / ldmatrix helpers (base ISA, sm_80+)
// ---------------------------------------------------------------------------
__device__ __forceinline__ uint32_t smem_u32(const void* p) {
    uint32_t a;
    asm("{ .reg .u64 t; cvta.to.shared.u64 t, %1; cvt.u32.u64 %0, t; }"
        : "=r"(a) : "l"(p));
    return a;
}

__device__ __forceinline__ void ldsm4(uint32_t addr, uint32_t r[4]) {
    asm volatile("ldmatrix.sync.aligned.m8n8.x4.shared.b16 {%0,%1,%2,%3}, [%4];"
                 : "=r"(r[0]), "=r"(r[1]), "=r"(r[2]), "=r"(r[3]) : "r"(addr));
}

__device__ __forceinline__ void mma16816(float c[4], const uint32_t a[4],
                                         const uint32_t b[2]) {
    asm volatile(
        "mma.sync.aligned.m16n8k16.row.col.f32.bf16.bf16.f32 "
        "{%0,%1,%2,%3}, {%4,%5,%6,%7}, {%8,%9}, {%0,%1,%2,%3};"
        : "+f"(c[0]), "+f"(c[1]), "+f"(c[2]), "+f"(c[3])
        : "r"(a[0]), "r"(a[1]), "r"(a[2]), "r"(a[3]), "r"(b[0]), "r"(b[1]));
}

__device__ __forceinline__ void split_bf16(float v, unsigned short& h, unsigned short& l) {
    __nv_bfloat16 hb = __float2bfloat16(v);
    float r = v - __bfloat162float(hb);
    __nv_bfloat16 lb = __float2bfloat16(r);
    h = *reinterpret_cast<unsigned short*>(&hb);
    l = *reinterpret_cast<unsigned short*>(&lb);
}

// ---------------------------------------------------------------------------
// prepB: split a fp32 [K][N] matrix (row stride Nsrc) into bf16 hi/lo tiles
// of ntileRows x 128 (k), per-tile layout [n_local][k].  grid = ntiles.
// (used for M only)
// ---------------------------------------------------------------------------
__global__ __launch_bounds__(256) void prepB(const float* __restrict__ src,
                                             int Ksrc, int Nsrc,
                                             unsigned short* __restrict__ dhi,
                                             unsigned short* __restrict__ dlo,
                                             int ntileRows) {
    const int nt = blockIdx.x;
    const int elems = ntileRows * 128;
    unsigned short* th = dhi + (size_t)nt * elems;
    unsigned short* tl = dlo + (size_t)nt * elems;
    for (int idx = threadIdx.x; idx < elems; idx += 256) {
        const int nl = idx >> 7, k = idx & 127;
        const int n = nt * ntileRows + nl;
        float v = (k < Ksrc) ? src[(size_t)k * Nsrc + n] : 0.f;
        unsigned short h, l;
        split_bf16(v, h, l);
        th[nl * 128 + k] = h;
        tl[nl * 128 + k] = l;
    }
}

// prep3: the three small B preps in one launch (grid 3).
// j=0: CyT -> YB rows 0-63 ; j=1: ACyT -> YB rows 64-127 ; j=2: KC -> KCT.
__global__ __launch_bounds__(256) void prep3(const float* __restrict__ CyT) {
    const int j = blockIdx.x;
    const float* src = (j == 0) ? CyT : (j == 1) ? g_ACyT : g_KC;
    const int Ksrc = (j == 2) ? 64 : 128;
    unsigned short* th = (j == 0) ? g_YB_hi : (j == 1) ? (g_YB_hi + 64 * 128) : g_KCT_hi;
    unsigned short* tl = (j == 0) ? g_YB_lo : (j == 1) ? (g_YB_lo + 64 * 128) : g_KCT_lo;
    for (int idx = threadIdx.x; idx < 64 * 128; idx += 256) {
        const int nl = idx >> 7, k = idx & 127;
        float v = (k < Ksrc) ? src[(size_t)k * 64 + nl] : 0.f;
        unsigned short h, l;
        split_bf16(v, h, l);
        th[nl * 128 + k] = h;
        tl[nl * 128 + k] = l;
    }
}

// ---------------------------------------------------------------------------
// hgemm: D[MROWS=64, NTILE] = A[64,128] @ B^T via mma.sync split-bf16.
// 2 CTAs/SM (smem 104448 / 69632).  8 warps: 2m x 4n, warp tile 32 x NTILE/4.
// MODE 0: out = g_Z rows (write)            grid (2048)        NTILE=128
// MODE 1: out = y, col base by*128 (write)   grid (64 mx,32 by) NTILE=128
// MODE 4: y[b,2i]   += . (A = x, B = KC)     grid (2048)        NTILE=64
// MODE 5: merged: n<64 -> y[2i+1] += S@CyT ; n>=64 -> y[2i+2] += S@ACyT
//         (skip chunk-last i for n>=64)      grid (2048)        NTILE=128
// ---------------------------------------------------------------------------
template <int NTILE, int MODE>
__global__ __launch_bounds__(256) void hgemm(const float* __restrict__ gA,
                                             const unsigned short* __restrict__ gBhi,
                                             const unsigned short* __restrict__ gBlo,
                                             float* __restrict__ out) {
    extern __shared__ __align__(16) char smc[];
    constexpr int A_ELE = MROWS * SSTRIDE;
    constexpr int B_ELE = NTILE * SSTRIDE;
    unsigned short* sAhi = (unsigned short*)smc;
    unsigned short* sAlo = sAhi + A_ELE;
    unsigned short* sBhi = sAlo + A_ELE;
    unsigned short* sBlo = sBhi + B_ELE;
    const uint32_t aAhi = smem_u32(sAhi), aAlo = smem_u32(sAlo);
    const uint32_t aBhi = smem_u32(sBhi), aBlo = smem_u32(sBlo);

    const int t = threadIdx.x;
    const int lane = t & 31, w = t >> 5;

    // ---- stage A: fp32 -> (hi,lo) bf16 rows [m][k] (64 rows) ----
    {
        const float4* Atile = (const float4*)(gA + (size_t)blockIdx.x * (MROWS * 128));
#pragma unroll
        for (int j = 0; j < 8; j++) {
            const int f = j * 256 + t;
            const float4 v = Atile[f];
            const int row = f >> 5, c = (f & 31) * 4;
            unsigned short h0, l0, h1, l1, h2, l2, h3, l3;
            split_bf16(v.x, h0, l0);
            split_bf16(v.y, h1, l1);
            split_bf16(v.z, h2, l2);
            split_bf16(v.w, h3, l3);
            const unsigned long long hh =
                (unsigned long long)h0 | ((unsigned long long)h1 << 16) |
                ((unsigned long long)h2 << 32) | ((unsigned long long)h3 << 48);
            const unsigned long long ll =
                (unsigned long long)l0 | ((unsigned long long)l1 << 16) |
                ((unsigned long long)l2 << 32) | ((unsigned long long)l3 << 48);
            *(unsigned long long*)(sAhi + row * SSTRIDE + c) = hh;
            *(unsigned long long*)(sAlo + row * SSTRIDE + c) = ll;
        }
    }
    // ---- stage B: copy pre-split tiles [n][128] -> padded smem ----
    {
        const size_t boff = (MODE == 1) ? (size_t)blockIdx.y * (NTILE * 128) : 0;
        const uint4* sh = (const uint4*)(gBhi + boff);
        const uint4* sl = (const uint4*)(gBlo + boff);
#pragma unroll
        for (int j = 0; j < NTILE / 16; j++) {
            const int f = j * 256 + t;                  // uint4 id (8 bf16)
            const int row = f >> 4, c = (f & 15) * 8;
            *(uint4*)(sBhi + row * SSTRIDE + c) = sh[f];
            *(uint4*)(sBlo + row * SSTRIDE + c) = sl[f];
        }
    }
    __syncthreads();

    // ---- warp tiling: 2m x 4n warps, warp tile 32 x NTILE/4 ----
    const int wm = w & 1, wn = w >> 1;
    const int m0w = wm * 32, n0w = wn * (NTILE / 4);
    constexpr int NF = NTILE / 32;                      // 8-col frags per warp

    float acc[2][NF][4];
#pragma unroll
    for (int i = 0; i < 2; i++)
#pragma unroll
        for (int j = 0; j < NF; j++)
#pragma unroll
            for (int q = 0; q < 4; q++) acc[i][j][q] = 0.f;

    const int aRow = lane & 15, aCol = (lane >> 4) * 8;
    const int bRow = (lane & 7) + ((lane >> 4) << 3), bCol = ((lane >> 3) & 1) * 8;

#pragma unroll
    for (int ks = 0; ks < 8; ks++) {
        const int k0 = ks * 16;
        uint32_t ahi[2][4], alo[2][4];
#pragma unroll
        for (int mf = 0; mf < 2; mf++) {
            const uint32_t off =
                (uint32_t)(((m0w + mf * 16 + aRow) * SSTRIDE + k0 + aCol) * 2);
            ldsm4(aAhi + off, ahi[mf]);
            ldsm4(aAlo + off, alo[mf]);
        }
        uint32_t bhi[NF][2], blo[NF][2];
#pragma unroll
        for (int nf2 = 0; nf2 < NF / 2; nf2++) {
            const uint32_t off =
                (uint32_t)(((n0w + nf2 * 16 + bRow) * SSTRIDE + k0 + bCol) * 2);
            uint32_t r[4];
            ldsm4(aBhi + off, r);
            bhi[nf2 * 2][0] = r[0]; bhi[nf2 * 2][1] = r[1];
            bhi[nf2 * 2 + 1][0] = r[2]; bhi[nf2 * 2 + 1][1] = r[3];
            ldsm4(aBlo + off, r);
            blo[nf2 * 2][0] = r[0]; blo[nf2 * 2][1] = r[1];
            blo[nf2 * 2 + 1][0] = r[2]; blo[nf2 * 2 + 1][1] = r[3];
        }
#pragma unroll
        for (int mf = 0; mf < 2; mf++)
#pragma unroll
            for (int nf = 0; nf < NF; nf++) {
                mma16816(acc[mf][nf], ahi[mf], bhi[nf]);
                mma16816(acc[mf][nf], ahi[mf], blo[nf]);
                mma16816(acc[mf][nf], alo[mf], bhi[nf]);
            }
    }

    // ---- epilogue ----
#pragma unroll
    for (int mf = 0; mf < 2; mf++) {
#pragma unroll
        for (int half = 0; half < 2; half++) {
            const int rloc = m0w + mf * 16 + (lane >> 2) + half * 8;
            const int r = blockIdx.x * MROWS + rloc;

            if (MODE == 5) {
                const int b = r >> 11, i = r & (HT - 1);
                const bool lastI = ((i & (HCH - 1)) == (HCH - 1));
                float* base1 = out + ((size_t)b * T_ + 2 * i + 1) * NOUT;
                float* base2 = out + ((size_t)b * T_ + 2 * i + 2) * NOUT;
#pragma unroll
                for (int nf = 0; nf < NF; nf++) {
                    const int n = n0w + nf * 8 + (lane & 3) * 2;
                    float* p;
                    if (n < 64) p = base1 + n;
                    else { if (lastI) continue; p = base2 + (n - 64); }
                    float2 v = make_float2(acc[mf][nf][half * 2],
                                           acc[mf][nf][half * 2 + 1]);
                    float2 e = *(float2*)p;
                    v.x += e.x; v.y += e.y;
                    *(float2*)p = v;
                }
                continue;
            }

            float* rowp;
            bool doacc = false;
            if (MODE == 0) {
                rowp = out + (size_t)r * 128;
            } else if (MODE == 1) {
                rowp = out + (size_t)r * 4096 + blockIdx.y * 128;
            } else {  // MODE 4
                const int b = r >> 11, i = r & (HT - 1);
                rowp = out + ((size_t)b * T_ + 2 * i) * NOUT;
                doacc = true;
            }
#pragma unroll
            for (int nf = 0; nf < NF; nf++) {
                const int cc = n0w + nf * 8 + (lane & 3) * 2;
                float2 v = make_float2(acc[mf][nf][half * 2],
                                       acc[mf][nf][half * 2 + 1]);
                float* p = rowp + cc;
                if (doacc) {
                    float2 e = *(float2*)p;
                    v.x += e.x; v.y += e.y;
                }
                *(float2*)p = v;
            }
        }
    }
}

// ---------------------------------------------------------------------------
// Small kernels (R6/R7-verified)
// ---------------------------------------------------------------------------
__global__ __launch_bounds__(128) void matsq(const float* __restrict__ A,
                                             float* __restrict__ O) {
    const int r = blockIdx.x, u = threadIdx.x;
    __shared__ float row[U_];
    row[u] = A[r * U_ + u];
    __syncthreads();
    float a0 = 0.f, a1 = 0.f, a2 = 0.f, a3 = 0.f;
#pragma unroll
    for (int k = 0; k < U_; k += 4) {
        a0 = fmaf(row[k + 0], A[(k + 0) * U_ + u], a0);
        a1 = fmaf(row[k + 1], A[(k + 1) * U_ + u], a1);
        a2 = fmaf(row[k + 2], A[(k + 2) * U_ + u], a2);
        a3 = fmaf(row[k + 3], A[(k + 3) * U_ + u], a3);
    }
    O[r * U_ + u] = (a0 + a1) + (a2 + a3);
}

__global__ __launch_bounds__(128) void buildM(const float* __restrict__ KT,
                                              const float* __restrict__ A) {
    const int r = blockIdx.x, u = threadIdx.x;
    __shared__ float row[U_];
    row[u] = KT[r * U_ + u];
    __syncthreads();
    float a0 = 0.f, a1 = 0.f, a2 = 0.f, a3 = 0.f;
#pragma unroll
    for (int k = 0; k < U_; k += 4) {
        a0 = fmaf(row[k + 0], A[(k + 0) * U_ + u], a0);
        a1 = fmaf(row[k + 1], A[(k + 1) * U_ + u], a1);
        a2 = fmaf(row[k + 2], A[(k + 2) * U_ + u], a2);
        a3 = fmaf(row[k + 3], A[(k + 3) * U_ + u], a3);
    }
    g_M[r * U_ + u] = (a0 + a1) + (a2 + a3);
    g_M[(64 + r) * U_ + u] = row[u];
}

__global__ __launch_bounds__(64) void buildSmall(const float* __restrict__ KT,
                                                 const float* __restrict__ A,
                                                 const float* __restrict__ CyT) {
    const int bid = blockIdx.x, o = threadIdx.x;
    __shared__ float row[U_];
    const float* src = (bid < 64) ? (KT + (size_t)bid * U_)
                                  : (A + (size_t)(bid - 64) * U_);
    row[o] = src[o];
    row[o + 64] = src[o + 64];
    __syncthreads();
    float a0 = 0.f, a1 = 0.f, a2 = 0.f, a3 = 0.f;
#pragma unroll
    for (int k = 0; k < U_; k += 4) {
        a0 = fmaf(row[k + 0], CyT[(k + 0) * NOUT + o], a0);
        a1 = fmaf(row[k + 1], CyT[(k + 1) * NOUT + o], a1);
        a2 = fmaf(row[k + 2], CyT[(k + 2) * NOUT + o], a2);
        a3 = fmaf(row[k + 3], CyT[(k + 3) * NOUT + o], a3);
    }
    const float v = (a0 + a1) + (a2 + a3);
    if (bid < 64) g_KC[bid * NOUT + o] = v;
    else          g_ACyT[(bid - 64) * NOUT + o] = v;
}

// scan (R6-verified): e_i = Z_i + e_{i-1}@A2, 32 steps, 16 batches/CTA
__global__ __launch_bounds__(128, 2) void scan_kernel() {
    const int c = blockIdx.x, bg = blockIdx.y, u = threadIdx.x;
    const int b0 = bg * 16;
    __shared__ __align__(16) float s_sh[2][U_ * 16];

    float at2[U_];
#pragma unroll
    for (int k = 0; k < U_; k++) at2[k] = g_A2[k * U_ + u];
#pragma unroll
    for (int j = 0; j < 16; j++) s_sh[0][u * 16 + j] = 0.f;
    __syncthreads();

    const int i0 = c * HCH;
    float zc[16];
#pragma unroll
    for (int j = 0; j < 16; j++)
        zc[j] = g_Z[((size_t)(b0 + j) * HT + i0) * U_ + u];

    int p = 0;
#pragma unroll 1
    for (int it = 0; it < HCH; it++) {
        const int i = i0 + it;
        float zn[16];
        if (it < HCH - 1) {
#pragma unroll
            for (int j = 0; j < 16; j++)
                zn[j] = g_Z[((size_t)(b0 + j) * HT + i + 1) * U_ + u];
        } else {
#pragma unroll
            for (int j = 0; j < 16; j++) zn[j] = 0.f;
        }

        unsigned long long acc[8];
#pragma unroll
        for (int q = 0; q < 8; q++) acc[q] = pack2(zc[2 * q], zc[2 * q + 1]);

#pragma unroll
        for (int k = 0; k < U_; k++) {
            const unsigned long long av = dup2(at2[k]);
            const ulonglong2 s0 = *(const ulonglong2*)&s_sh[p][k * 16 + 0];
            const ulonglong2 s1 = *(const ulonglong2*)&s_sh[p][k * 16 + 4];
            const ulonglong2 s2 = *(const ulonglong2*)&s_sh[p][k * 16 + 8];
            const ulonglong2 s3 = *(const ulonglong2*)&s_sh[p][k * 16 + 12];
            acc[0] = ffma2(s0.x, av, acc[0]);
            acc[1] = ffma2(s0.y, av, acc[1]);
            acc[2] = ffma2(s1.x, av, acc[2]);
            acc[3] = ffma2(s1.y, av, acc[3]);
            acc[4] = ffma2(s2.x, av, acc[4]);
            acc[5] = ffma2(s2.y, av, acc[5]);
            acc[6] = ffma2(s3.x, av, acc[6]);
            acc[7] = ffma2(s3.y, av, acc[7]);
        }

        const int q = p ^ 1;
        float2 f0 = unpack2(acc[0]), f1 = unpack2(acc[1]);
        float2 f2 = unpack2(acc[2]), f3 = unpack2(acc[3]);
        float2 f4 = unpack2(acc[4]), f5 = unpack2(acc[5]);
        float2 f6 = unpack2(acc[6]), f7 = unpack2(acc[7]);
        {
            float4* dst = (float4*)&s_sh[q][u * 16];
            dst[0] = make_float4(f0.x, f0.y, f1.x, f1.y);
            dst[1] = make_float4(f2.x, f2.y, f3.x, f3.y);
            dst[2] = make_float4(f4.x, f4.y, f5.x, f5.y);
            dst[3] = make_float4(f6.x, f6.y, f7.x, f7.y);
        }
        g_S[((size_t)(b0 + 0)  * HT + i) * U_ + u] = f0.x;
        g_S[((size_t)(b0 + 1)  * HT + i) * U_ + u] = f0.y;
        g_S[((size_t)(b0 + 2)  * HT + i) * U_ + u] = f1.x;
        g_S[((size_t)(b0 + 3)  * HT + i) * U_ + u] = f1.y;
        g_S[((size_t)(b0 + 4)  * HT + i) * U_ + u] = f2.x;
        g_S[((size_t)(b0 + 5)  * HT + i) * U_ + u] = f2.y;
        g_S[((size_t)(b0 + 6)  * HT + i) * U_ + u] = f3.x;
        g_S[((size_t)(b0 + 7)  * HT + i) * U_ + u] = f3.y;
        g_S[((size_t)(b0 + 8)  * HT + i) * U_ + u] = f4.x;
        g_S[((size_t)(b0 + 9)  * HT + i) * U_ + u] = f4.y;
        g_S[((size_t)(b0 + 10) * HT + i) * U_ + u] = f5.x;
        g_S[((size_t)(b0 + 11) * HT + i) * U_ + u] = f5.y;
        g_S[((size_t)(b0 + 12) * HT + i) * U_ + u] = f6.x;
        g_S[((size_t)(b0 + 13) * HT + i) * U_ + u] = f6.y;
        g_S[((size_t)(b0 + 14) * HT + i) * U_ + u] = f7.x;
        g_S[((size_t)(b0 + 15) * HT + i) * U_ + u] = f7.y;
        __syncthreads();

        p = q;
#pragma unroll
        for (int j = 0; j < 16; j++) zc[j] = zn[j];
    }
}

__global__ __launch_bounds__(128) void pass2_kernel() {
    const int b = blockIdx.x, u = threadIdx.x;
    __shared__ float ss[2][U_];
    float m[U_];
#pragma unroll
    for (int k = 0; k < U_; k++) m[k] = g_A64[k * U_ + u];

    float su = 0.f;
    float e = g_S[((size_t)b * HT + (HCH - 1)) * U_ + u];
    ss[0][u] = 0.f;
    __syncthreads();

    int p = 0;
#pragma unroll 1
    for (int c = 0; c < CCH; c++) {
        g_carry[((size_t)b * CCH + c) * U_ + u] = su;
        float a0 = e, a1 = 0.f, a2 = 0.f, a3 = 0.f;
        if (c < CCH - 1)
            e = g_S[((size_t)b * HT + (c + 1) * HCH + (HCH - 1)) * U_ + u];
#pragma unroll
        for (int k = 0; k < U_; k += 4) {
            a0 = fmaf(ss[p][k + 0], m[k + 0], a0);
            a1 = fmaf(ss[p][k + 1], m[k + 1], a1);
            a2 = fmaf(ss[p][k + 2], m[k + 2], a2);
            a3 = fmaf(ss[p][k + 3], m[k + 3], a3);
        }
        su = (a0 + a1) + (a2 + a3);
        ss[p ^ 1][u] = su;
        __syncthreads();
        p ^= 1;
    }
}

// ---------------------------------------------------------------------------
// wbuild: CTA s computes W[s] = A^(s+1)@CyT via binary power chain, then
// writes split bf16 hi/lo DIRECTLY into g_WT_hi/lo tiles (coalesced along k).
// ---------------------------------------------------------------------------
__global__ __launch_bounds__(512) void wbuild(const float* __restrict__ A1,
                                              const float* __restrict__ CyT) {
    extern __shared__ float V[];
    float* cur = V;
    float* nxt = V + 8192;
    const int s = blockIdx.x;
    const int n = s + 1;
    const int tid = threadIdx.x;
    const int o = tid & 63, kg = tid >> 6;

    for (int i = tid; i < U_ * NOUT; i += 512) cur[i] = CyT[i];
    __syncthreads();

#pragma unroll 1
    for (int b = 0; b < 7; b++) {
        if (!((n >> b) & 1)) continue;
        const float* P = (b == 0) ? A1
                       : (b == 1) ? g_A2  : (b == 2) ? g_A4
                       : (b == 3) ? g_A8  : (b == 4) ? g_A16
                       : (b == 5) ? g_A32 : g_A64;
#pragma unroll 1
        for (int i = 0; i < 16; i++) {
            const int k = kg * 16 + i;
            float a0 = 0.f, a1 = 0.f, a2 = 0.f, a3 = 0.f;
#pragma unroll
            for (int m = 0; m < U_; m += 4) {
                a0 = fmaf(P[k * U_ + m + 0], cur[(m + 0) * 64 + o], a0);
                a1 = fmaf(P[k * U_ + m + 1], cur[(m + 1) * 64 + o], a1);
                a2 = fmaf(P[k * U_ + m + 2], cur[(m + 2) * 64 + o], a2);
                a3 = fmaf(P[k * U_ + m + 3], cur[(m + 3) * 64 + o], a3);
            }
            nxt[k * 64 + o] = (a0 + a1) + (a2 + a3);
        }
        __syncthreads();
        float* tmp = cur; cur = nxt; nxt = tmp;
    }

    {
        unsigned short* th = g_WT_hi + (size_t)(s >> 1) * 16384;
        unsigned short* tl = g_WT_lo + (size_t)(s >> 1) * 16384;
        const int nbase = (s & 1) * 64;
#pragma unroll 1
        for (int idx = tid; idx < 8192; idx += 512) {
            const int k = idx & 127, oo = idx >> 7;
            unsigned short h, l;
            split_bf16(cur[k * 64 + oo], h, l);
            th[(nbase + oo) * 128 + k] = h;
            tl[(nbase + oo) * 128 + k] = l;
        }
    }
}

// ---------------------------------------------------------------------------
// Launch.  #4 = hgemm<128,0> (zbuild) — the ncu-profiled slot.
// ---------------------------------------------------------------------------
extern "C" void kernel_launch(void* const* d_in, const int* in_sizes, int n_in,
                              void* d_out, int out_size) {
    const float* x   = (const float*)d_in[0];
    const float* AT  = (const float*)d_in[1];
    const float* KT  = (const float*)d_in[2];
    const float* CyT = (const float*)d_in[3];
    float* y = (float*)d_out;

    float *A2, *A4, *A8, *A16, *A32, *A64, *pM, *pZ, *pS, *pCar;
    unsigned short *MTh, *MTl, *WTh, *WTl, *YBh, *YBl, *KCTh, *KCTl;
    cudaGetSymbolAddress((void**)&A2,  g_A2);
    cudaGetSymbolAddress((void**)&A4,  g_A4);
    cudaGetSymbolAddress((void**)&A8,  g_A8);
    cudaGetSymbolAddress((void**)&A16, g_A16);
    cudaGetSymbolAddress((void**)&A32, g_A32);
    cudaGetSymbolAddress((void**)&A64, g_A64);
    cudaGetSymbolAddress((void**)&pM,  g_M);
    cudaGetSymbolAddress((void**)&pZ,  g_Z);
    cudaGetSymbolAddress((void**)&pS,  g_S);
    cudaGetSymbolAddress((void**)&pCar, g_carry);
    cudaGetSymbolAddress((void**)&MTh, g_MT_hi);  cudaGetSymbolAddress((void**)&MTl, g_MT_lo);
    cudaGetSymbolAddress((void**)&WTh, g_WT_hi);  cudaGetSymbolAddress((void**)&WTl, g_WT_lo);
    cudaGetSymbolAddress((void**)&YBh, g_YB_hi);  cudaGetSymbolAddress((void**)&YBl, g_YB_lo);
    cudaGetSymbolAddress((void**)&KCTh, g_KCT_hi); cudaGetSymbolAddress((void**)&KCTl, g_KCT_lo);

    // smem: A(64 rows) hi/lo + B(NTILE) hi/lo, padded bf16
    const int SM128 = (2 * MROWS * SSTRIDE + 2 * 128 * SSTRIDE) * 2;  // 104448
    const int SM64  = (2 * MROWS * SSTRIDE + 2 * 64 * SSTRIDE) * 2;   // 69632
    cudaFuncSetAttribute(hgemm<128, 0>, cudaFuncAttributeMaxDynamicSharedMemorySize, SM128);
    cudaFuncSetAttribute(hgemm<128, 1>, cudaFuncAttributeMaxDynamicSharedMemorySize, SM128);
    cudaFuncSetAttribute(hgemm<128, 5>, cudaFuncAttributeMaxDynamicSharedMemorySize, SM128);
    cudaFuncSetAttribute(hgemm<64, 4>,  cudaFuncAttributeMaxDynamicSharedMemorySize, SM64);
    cudaFuncSetAttribute(wbuild, cudaFuncAttributeMaxDynamicSharedMemorySize, 65536);

    buildM<<<64, 128>>>(KT, AT);                               // 1
    matsq<<<128, 128>>>(AT, A2);                               // 2
    prepB<<<1, 256>>>(pM, 128, 128, MTh, MTl, 128);            // 3
    hgemm<128, 0><<<2048, 256, SM128>>>(x, MTh, MTl, pZ);      // 4  <- ncu
    scan_kernel<<<dim3(CCH, 4), 128>>>();                      // 5
    matsq<<<128, 128>>>(A2,  A4);                              // 6
    matsq<<<128, 128>>>(A4,  A8);                              // 7
    matsq<<<128, 128>>>(A8,  A16);                             // 8
    matsq<<<128, 128>>>(A16, A32);                             // 9
    matsq<<<128, 128>>>(A32, A64);                             // 10
    buildSmall<<<192, 64>>>(KT, AT, CyT);                      // 11
    prep3<<<3, 256>>>(CyT);                                    // 12
    pass2_kernel<<<B_, 128>>>();                               // 13
    wbuild<<<LCH, 512, 65536>>>(AT, CyT);                      // 14 (writes WT direct)
    hgemm<128, 1><<<dim3(64, 32), 256, SM128>>>(pCar, WTh, WTl, y);  // 15 (writes y)
    hgemm<64, 4><<<2048, 256, SM64>>>(x,  KCTh, KCTl, y);      // 16 (+= even)
    hgemm<128, 5><<<2048, 256, SM128>>>(pS, YBh, YBl, y);      // 17 (+= odd & even+2)
}